// round 9
// baseline (speedup 1.0000x reference)
#include <cuda_runtime.h>
#include <cuda_bf16.h>
#include <cstdint>

// ---------------- problem constants ----------------
constexpr int Lc = 2048, Ec = 1024, Hc = 16, Dc = 64, Bc = 2;
constexpr int BHc = Bc * Hc;     // 32
constexpr int Mr  = Bc * Lc;     // 4096

// ---------------- device scratch ----------------
__device__ __nv_bfloat16 g_xhi[Mr * Ec],  g_xlo[Mr * Ec];
__device__ __nv_bfloat16 g_wthi[3 * Ec * Ec], g_wtlo[3 * Ec * Ec];
__device__ __nv_bfloat16 g_qhi[BHc * Lc * Dc], g_qlo[BHc * Lc * Dc];
__device__ __nv_bfloat16 g_khi[BHc * Lc * Dc], g_klo[BHc * Lc * Dc];
__device__ float         g_v  [BHc * Lc * Dc];
__device__ __nv_bfloat16 g_vthi[BHc * Dc * Lc], g_vtlo[BHc * Dc * Lc];
__device__ __nv_bfloat16 g_ehi[(size_t)BHc * Lc * Lc];   // 268MB
__device__ __nv_bfloat16 g_elo[(size_t)BHc * Lc * Lc];   // 268MB
__device__ float         g_psum[(size_t)BHc * 16 * Lc];

// ---------------- helpers ----------------
__device__ __forceinline__ uint32_t smem_u32(const void* p) {
    uint32_t a;
    asm("{ .reg .u64 t; cvta.to.shared.u64 t, %1; cvt.u32.u64 %0, t; }" : "=r"(a) : "l"(p));
    return a;
}
__device__ __forceinline__ void split_bf(float f, __nv_bfloat16& h, __nv_bfloat16& l) {
    h = __float2bfloat16(f);
    l = __float2bfloat16(f - __bfloat162float(h));
}
__device__ __forceinline__ void pack_hilo(float f0, float f1, uint32_t& ph, uint32_t& pl) {
    asm("cvt.rn.bf16x2.f32 %0, %1, %2;" : "=r"(ph) : "f"(f1), "f"(f0));
    float h0 = __uint_as_float(ph << 16);
    float h1 = __uint_as_float(ph & 0xFFFF0000u);
    float r0 = f0 - h0, r1 = f1 - h1;
    asm("cvt.rn.bf16x2.f32 %0, %1, %2;" : "=r"(pl) : "f"(r1), "f"(r0));
}
__device__ __forceinline__ void cp16(uint32_t dst, const void* src) {
    asm volatile("cp.async.cg.shared.global [%0], [%1], 16;" :: "r"(dst), "l"(src));
}
__device__ __forceinline__ void cp_commit() { asm volatile("cp.async.commit_group;"); }
template<int N> __device__ __forceinline__ void cp_wait() {
    asm volatile("cp.async.wait_group %0;" :: "n"(N));
}
#define LDSM4(r, addr) \
    asm volatile("ldmatrix.sync.aligned.m8n8.x4.shared.b16 {%0,%1,%2,%3}, [%4];" \
        : "=r"((r)[0]), "=r"((r)[1]), "=r"((r)[2]), "=r"((r)[3]) : "r"(addr))
#define MMA(d, a, b) \
    asm volatile("mma.sync.aligned.m16n8k16.row.col.f32.bf16.bf16.f32 " \
        "{%0,%1,%2,%3}, {%4,%5,%6,%7}, {%8,%9}, {%0,%1,%2,%3};" \
        : "+f"((d)[0]), "+f"((d)[1]), "+f"((d)[2]), "+f"((d)[3]) \
        : "r"((a)[0]), "r"((a)[1]), "r"((a)[2]), "r"((a)[3]), "r"((b)[0]), "r"((b)[1]))

// ---------------- generic 3-term bf16 GEMM core (2-stage) ----------------
template<int BM, int BN, int WGN, int WM, int BKt>
__device__ __forceinline__ void gemm_core(
    const __nv_bfloat16* __restrict__ Ahi, const __nv_bfloat16* __restrict__ Alo, int lda,
    const __nv_bfloat16* __restrict__ Bhi, const __nv_bfloat16* __restrict__ Blo, int ldb,
    int K, uint32_t sb, float* acc)
{
    constexpr int WNB = BN / WGN;
    constexpr int MT  = WM / 16;
    constexpr int NT  = WNB / 8;
    constexpr int PITCH = BKt * 2 + 16;
    constexpr int CPR = BKt / 8;
    constexpr int ABY = BM * PITCH;
    constexpr int BBY = BN * PITCH;
    constexpr int STG = 2 * ABY + 2 * BBY;

    const int tid = threadIdx.x;
    const int wid = tid >> 5, lane = tid & 31;
    const int wm = wid / WGN, wn = wid % WGN;

    auto issue = [&](int it, int buf) {
        const int k0 = it * BKt;
        const uint32_t base = sb + buf * STG;
        #pragma unroll
        for (int c = tid; c < BM * CPR; c += 256) {
            int row = c / CPR, seg = c % CPR;
            uint32_t d = base + row * PITCH + seg * 16;
            cp16(d,       Ahi + (size_t)row * lda + k0 + seg * 8);
            cp16(d + ABY, Alo + (size_t)row * lda + k0 + seg * 8);
        }
        #pragma unroll
        for (int c = tid; c < BN * CPR; c += 256) {
            int row = c / CPR, seg = c % CPR;
            uint32_t d = base + 2 * ABY + row * PITCH + seg * 16;
            cp16(d,       Bhi + (size_t)row * ldb + k0 + seg * 8);
            cp16(d + BBY, Blo + (size_t)row * ldb + k0 + seg * 8);
        }
        cp_commit();
    };

    auto compute = [&](int buf) {
        const uint32_t aB = sb + buf * STG +
            (uint32_t)((wm * WM + (lane & 15)) * PITCH + ((lane >> 4) << 4));
        const uint32_t bB = sb + buf * STG + 2 * ABY +
            (uint32_t)((wn * WNB + (lane & 7) + (((lane >> 4) & 1) << 3)) * PITCH +
                       (((lane >> 3) & 1) << 4));
        #pragma unroll
        for (int ks = 0; ks < BKt / 16; ks++) {
            uint32_t ah[MT][4], al[MT][4];
            #pragma unroll
            for (int mt = 0; mt < MT; mt++) {
                LDSM4(ah[mt], aB + mt * 16 * PITCH + ks * 32);
                LDSM4(al[mt], aB + ABY + mt * 16 * PITCH + ks * 32);
            }
            uint32_t bh[NT][2], bl[NT][2];
            #pragma unroll
            for (int np = 0; np < NT / 2; np++) {
                uint32_t t[4];
                LDSM4(t, bB + np * 16 * PITCH + ks * 32);
                bh[2*np][0] = t[0]; bh[2*np][1] = t[1];
                bh[2*np+1][0] = t[2]; bh[2*np+1][1] = t[3];
                LDSM4(t, bB + BBY + np * 16 * PITCH + ks * 32);
                bl[2*np][0] = t[0]; bl[2*np][1] = t[1];
                bl[2*np+1][0] = t[2]; bl[2*np+1][1] = t[3];
            }
            #pragma unroll
            for (int mt = 0; mt < MT; mt++)
                #pragma unroll
                for (int nt = 0; nt < NT; nt++) {
                    float* d = acc + (mt * NT + nt) * 4;
                    MMA(d, ah[mt], bh[nt]);
                    MMA(d, ah[mt], bl[nt]);
                    MMA(d, al[mt], bh[nt]);
                }
        }
    };

    const int niter = K / BKt;
    issue(0, 0);
    for (int it = 0; it < niter; it++) {
        if (it + 1 < niter) { issue(it + 1, (it + 1) & 1); cp_wait<1>(); }
        else                { cp_wait<0>(); }
        __syncthreads();
        compute(it & 1);
        __syncthreads();
    }
}

// ---------------- conversion kernels ----------------
__global__ void conv_x(const float* __restrict__ x) {
    int i = blockIdx.x * 256 + threadIdx.x;
    float4 v = reinterpret_cast<const float4*>(x)[i];
    uint32_t h01, l01, h23, l23;
    pack_hilo(v.x, v.y, h01, l01);
    pack_hilo(v.z, v.w, h23, l23);
    reinterpret_cast<uint32_t*>(g_xhi)[i * 2]     = h01;
    reinterpret_cast<uint32_t*>(g_xhi)[i * 2 + 1] = h23;
    reinterpret_cast<uint32_t*>(g_xlo)[i * 2]     = l01;
    reinterpret_cast<uint32_t*>(g_xlo)[i * 2 + 1] = l23;
}

__global__ void conv_w(const float* __restrict__ Wq, const float* __restrict__ Wk,
                       const float* __restrict__ Wv) {
    const float* W = (blockIdx.z == 0) ? Wq : (blockIdx.z == 1) ? Wk : Wv;
    __nv_bfloat16* dh = g_wthi + (size_t)blockIdx.z * Ec * Ec;
    __nv_bfloat16* dl = g_wtlo + (size_t)blockIdx.z * Ec * Ec;
    __shared__ float t[32][33];
    int tx = threadIdx.x, ty = threadIdx.y;
    int k0 = blockIdx.x * 32, n0 = blockIdx.y * 32;
    #pragma unroll
    for (int i = 0; i < 4; i++)
        t[ty + i * 8][tx] = W[(size_t)(k0 + ty + i * 8) * Ec + n0 + tx];
    __syncthreads();
    #pragma unroll
    for (int i = 0; i < 4; i++) {
        float v = t[tx][ty + i * 8];
        __nv_bfloat16 h, l; split_bf(v, h, l);
        size_t o = (size_t)(n0 + ty + i * 8) * Ec + k0 + tx;
        dh[o] = h; dl[o] = l;
    }
}

// ---------------- GEMM 1: QKV projection (128x128 tile) ----------------
__global__ void __launch_bounds__(256) k_proj_t(const float* __restrict__ bq,
                                                const float* __restrict__ bk,
                                                const float* __restrict__ bv) {
    extern __shared__ char smem[];
    uint32_t sb = smem_u32(smem);
    const int tid = threadIdx.x;
    const int z = blockIdx.z;
    const int n0 = blockIdx.x * 128, m0 = blockIdx.y * 128;
    const float* bias = (z == 0) ? bq : (z == 1) ? bk : bv;
    const __nv_bfloat16* Whi = g_wthi + (size_t)z * Ec * Ec;
    const __nv_bfloat16* Wlo = g_wtlo + (size_t)z * Ec * Ec;

    float acc[64] = {};
    gemm_core<128, 128, 4, 64, 32>(g_xhi + (size_t)m0 * Ec, g_xlo + (size_t)m0 * Ec, Ec,
                                   Whi + (size_t)n0 * Ec,   Wlo + (size_t)n0 * Ec,   Ec,
                                   Ec, sb, acc);

    float* stage = reinterpret_cast<float*>(smem);   // 128 x pitch130
    const int wid = tid >> 5, lane = tid & 31;
    const int wm = wid >> 2, wn = wid & 3;
    #pragma unroll
    for (int mt = 0; mt < 4; mt++)
        #pragma unroll
        for (int nt = 0; nt < 4; nt++) {
            int r0 = wm * 64 + mt * 16 + (lane >> 2);
            int c0 = wn * 32 + nt * 8 + (lane & 3) * 2;
            float* d = acc + (mt * 4 + nt) * 4;
            stage[r0 * 130 + c0] = d[0]; stage[r0 * 130 + c0 + 1] = d[1];
            stage[(r0 + 8) * 130 + c0] = d[2]; stage[(r0 + 8) * 130 + c0 + 1] = d[3];
        }
    __syncthreads();

    if (z < 2) {
        __nv_bfloat16* dh = (z == 0) ? g_qhi : g_khi;
        __nv_bfloat16* dl = (z == 0) ? g_qlo : g_klo;
        #pragma unroll
        for (int head = 0; head < 2; head++) {
            int h = (n0 >> 6) + head;
            for (int c = tid; c < 1024; c += 256) {
                int row = c >> 3, seg = c & 7;
                int m = m0 + row, b = m >> 11, l = m & 2047;
                uint32_t ph[4], pl[4];
                #pragma unroll
                for (int j = 0; j < 4; j++) {
                    float f0 = stage[row * 130 + head * 64 + seg * 8 + 2 * j] +
                               bias[n0 + head * 64 + seg * 8 + 2 * j];
                    float f1 = stage[row * 130 + head * 64 + seg * 8 + 2 * j + 1] +
                               bias[n0 + head * 64 + seg * 8 + 2 * j + 1];
                    pack_hilo(f0, f1, ph[j], pl[j]);
                }
                size_t o = ((size_t)(b * Hc + h) * Lc + l) * Dc + seg * 8;
                *reinterpret_cast<uint4*>(dh + o) = make_uint4(ph[0], ph[1], ph[2], ph[3]);
                *reinterpret_cast<uint4*>(dl + o) = make_uint4(pl[0], pl[1], pl[2], pl[3]);
            }
        }
    } else {
        for (int c = tid; c < 4096; c += 256) {
            int row = c >> 5, sg = c & 31;
            int head = sg >> 4, seg = sg & 15;
            int m = m0 + row, b = m >> 11, l = m & 2047;
            int h = (n0 >> 6) + head;
            float4 v;
            v.x = stage[row * 130 + head * 64 + seg * 4 + 0] + bias[n0 + head * 64 + seg * 4 + 0];
            v.y = stage[row * 130 + head * 64 + seg * 4 + 1] + bias[n0 + head * 64 + seg * 4 + 1];
            v.z = stage[row * 130 + head * 64 + seg * 4 + 2] + bias[n0 + head * 64 + seg * 4 + 2];
            v.w = stage[row * 130 + head * 64 + seg * 4 + 3] + bias[n0 + head * 64 + seg * 4 + 3];
            *reinterpret_cast<float4*>(g_v + ((size_t)(b * Hc + h) * Lc + l) * Dc + seg * 4) = v;
        }
    }
}

// ---------------- GEMM 2: scores + exp + colsums, DIRECT E writes ----------------
__global__ void __launch_bounds__(256) k_scores_t() {
    extern __shared__ char smem[];
    uint32_t sb = smem_u32(smem);
    const int tid = threadIdx.x;
    const int bh = blockIdx.z, m0 = blockIdx.x * 128, l0 = blockIdx.y * 128;

    float acc[64] = {};
    gemm_core<128, 128, 4, 64, 32>(g_qhi + ((size_t)bh * Lc + l0) * Dc,
                                   g_qlo + ((size_t)bh * Lc + l0) * Dc, Dc,
                                   g_khi + ((size_t)bh * Lc + m0) * Dc,
                                   g_klo + ((size_t)bh * Lc + m0) * Dc, Dc,
                                   Dc, sb, acc);

    float* colp = reinterpret_cast<float*>(smem);    // [2][128] (after mainloop sync)
    const int wid = tid >> 5, lane = tid & 31;
    const int wm = wid >> 2, wn = wid & 3;

    // base pointers for this thread's E region
    const size_t rowstride = Lc;   // elements
    __nv_bfloat16* ehiB = g_ehi + ((size_t)bh * Lc + l0) * Lc + m0;
    __nv_bfloat16* eloB = g_elo + ((size_t)bh * Lc + l0) * Lc + m0;

    float cs[4][2] = {};
    #pragma unroll
    for (int mt = 0; mt < 4; mt++)
        #pragma unroll
        for (int nt = 0; nt < 4; nt++) {
            float* d = acc + (mt * 4 + nt) * 4;
            int r0 = wm * 64 + mt * 16 + (lane >> 2);
            int cp = wn * 16 + nt * 4 + (lane & 3);
            float e0 = __expf(d[0]), e1 = __expf(d[1]);
            float e2 = __expf(d[2]), e3 = __expf(d[3]);
            cs[nt][0] += e0 + e2;
            cs[nt][1] += e1 + e3;
            uint32_t ph, pl;
            pack_hilo(e0, e1, ph, pl);
            *reinterpret_cast<uint32_t*>(ehiB + (size_t)r0 * rowstride + cp * 2) = ph;
            *reinterpret_cast<uint32_t*>(eloB + (size_t)r0 * rowstride + cp * 2) = pl;
            pack_hilo(e2, e3, ph, pl);
            *reinterpret_cast<uint32_t*>(ehiB + (size_t)(r0 + 8) * rowstride + cp * 2) = ph;
            *reinterpret_cast<uint32_t*>(eloB + (size_t)(r0 + 8) * rowstride + cp * 2) = pl;
        }

    // reduce colsums across the 8 lanes sharing each column pair
    #pragma unroll
    for (int nt = 0; nt < 4; nt++)
        #pragma unroll
        for (int p = 0; p < 2; p++) {
            float v = cs[nt][p];
            v += __shfl_xor_sync(0xffffffffu, v, 4);
            v += __shfl_xor_sync(0xffffffffu, v, 8);
            v += __shfl_xor_sync(0xffffffffu, v, 16);
            cs[nt][p] = v;
        }
    if (lane < 4) {
        #pragma unroll
        for (int nt = 0; nt < 4; nt++) {
            int cp = wn * 16 + nt * 4 + lane;
            colp[wm * 128 + cp * 2]     = cs[nt][0];
            colp[wm * 128 + cp * 2 + 1] = cs[nt][1];
        }
    }
    __syncthreads();
    if (tid < 128)
        g_psum[((size_t)bh * 16 + blockIdx.y) * Lc + m0 + tid] = colp[tid] + colp[128 + tid];
}

// ---------------- Vs^T = (V * dinv)^T as bf16 hi/lo (dinv fused) ----------------
__global__ void k_vscale() {
    __shared__ float tv[64][65];
    __shared__ float dsm[64];
    int tid = threadIdx.x;
    int bh = blockIdx.y, m0 = blockIdx.x * 64;
    if (tid < 64) {
        float s = 0.0f;
        #pragma unroll
        for (int j = 0; j < 16; j++) s += g_psum[((size_t)bh * 16 + j) * Lc + m0 + tid];
        dsm[tid] = 1.0f / s;
    }
    __syncthreads();
    const float* V = g_v + ((size_t)bh * Lc + m0) * Dc;
    #pragma unroll
    for (int i = 0; i < 16; i++) {
        int e = tid + i * 256;
        int r = e >> 6, d = e & 63;
        tv[r][d] = V[r * Dc + d] * dsm[r];
    }
    __syncthreads();
    #pragma unroll
    for (int i = 0; i < 16; i++) {
        int e = tid + i * 256;
        int d = e >> 6, c = e & 63;
        float v = tv[c][d];
        __nv_bfloat16 h, l; split_bf(v, h, l);
        size_t o = ((size_t)bh * Dc + d) * Lc + m0 + c;
        g_vthi[o] = h; g_vtlo[o] = l;
    }
}

// ---------------- GEMM 3: out = E * Vs^T (128x64, BK=64) ----------------
__global__ void __launch_bounds__(256) k_pv_t(float* __restrict__ outF) {
    extern __shared__ char smem[];
    uint32_t sb = smem_u32(smem);
    const int tid = threadIdx.x;
    const int bh = blockIdx.y, b = bh >> 4, h = bh & 15;
    const int l0 = blockIdx.x * 128;

    float acc[32] = {};
    gemm_core<128, 64, 2, 32, 64>(g_ehi + ((size_t)bh * Lc + l0) * Lc,
                                  g_elo + ((size_t)bh * Lc + l0) * Lc, Lc,
                                  g_vthi + (size_t)bh * Dc * Lc,
                                  g_vtlo + (size_t)bh * Dc * Lc,       Lc,
                                  Lc, sb, acc);

    float* stage = reinterpret_cast<float*>(smem);     // 128 x pitch68
    const int wid = tid >> 5, lane = tid & 31;
    const int wm = wid >> 1, wn = wid & 1;
    #pragma unroll
    for (int mt = 0; mt < 2; mt++)
        #pragma unroll
        for (int nt = 0; nt < 4; nt++) {
            int r0 = wm * 32 + mt * 16 + (lane >> 2);
            int c0 = wn * 32 + nt * 8 + (lane & 3) * 2;
            float* d = acc + (mt * 4 + nt) * 4;
            stage[r0 * 68 + c0] = d[0]; stage[r0 * 68 + c0 + 1] = d[1];
            stage[(r0 + 8) * 68 + c0] = d[2]; stage[(r0 + 8) * 68 + c0 + 1] = d[3];
        }
    __syncthreads();
    for (int c = tid; c < 2048; c += 256) {
        int row = c >> 4, seg = c & 15;
        float4 v = *reinterpret_cast<float4*>(&stage[row * 68 + seg * 4]);
        *reinterpret_cast<float4*>(outF + ((size_t)b * Lc + l0 + row) * Ec + h * Dc + seg * 4) = v;
    }
}

// ---------------- launch ----------------
extern "C" void kernel_launch(void* const* d_in, const int* in_sizes, int n_in,
                              void* d_out, int out_size) {
    const float* x  = (const float*)d_in[0];
    const float* Wq = (const float*)d_in[1];
    const float* bq = (const float*)d_in[2];
    const float* Wk = (const float*)d_in[3];
    const float* bk = (const float*)d_in[4];
    const float* Wv = (const float*)d_in[5];
    const float* bv = (const float*)d_in[6];
    float* out = (float*)d_out;

    cudaFuncSetAttribute(k_proj_t,   cudaFuncAttributeMaxDynamicSharedMemorySize, 81920);
    cudaFuncSetAttribute(k_scores_t, cudaFuncAttributeMaxDynamicSharedMemorySize, 81920);
    cudaFuncSetAttribute(k_pv_t,     cudaFuncAttributeMaxDynamicSharedMemorySize, 110592);

    conv_x<<<Mr * Ec / 1024, 256>>>(x);
    conv_w<<<dim3(32, 32, 3), dim3(32, 8)>>>(Wq, Wk, Wv);
    k_proj_t<<<dim3(8, 32, 3), 256, 81920>>>(bq, bk, bv);
    k_scores_t<<<dim3(16, 16, 32), 256, 81920>>>();
    k_vscale<<<dim3(32, 32), 256>>>();
    k_pv_t<<<dim3(16, 32), 256, 110592>>>(out);
}

// round 10
// speedup vs baseline: 1.0388x; 1.0388x over previous
#include <cuda_runtime.h>
#include <cuda_bf16.h>
#include <cstdint>

// ---------------- problem constants ----------------
constexpr int Lc = 2048, Ec = 1024, Hc = 16, Dc = 64, Bc = 2;
constexpr int BHc = Bc * Hc;     // 32
constexpr int Mr  = Bc * Lc;     // 4096

// ---------------- device scratch ----------------
__device__ __nv_bfloat16 g_xhi[Mr * Ec],  g_xlo[Mr * Ec];
__device__ __nv_bfloat16 g_wthi[3 * Ec * Ec], g_wtlo[3 * Ec * Ec];
__device__ __nv_bfloat16 g_qhi[BHc * Lc * Dc], g_qlo[BHc * Lc * Dc];
__device__ __nv_bfloat16 g_khi[BHc * Lc * Dc], g_klo[BHc * Lc * Dc];
__device__ float         g_v  [BHc * Lc * Dc];
__device__ __nv_bfloat16 g_vthi[BHc * Dc * Lc], g_vtlo[BHc * Dc * Lc];
__device__ float         g_psum[(size_t)BHc * 16 * Lc];

// ---------------- helpers ----------------
__device__ __forceinline__ uint32_t smem_u32(const void* p) {
    uint32_t a;
    asm("{ .reg .u64 t; cvta.to.shared.u64 t, %1; cvt.u32.u64 %0, t; }" : "=r"(a) : "l"(p));
    return a;
}
__device__ __forceinline__ void split_bf(float f, __nv_bfloat16& h, __nv_bfloat16& l) {
    h = __float2bfloat16(f);
    l = __float2bfloat16(f - __bfloat162float(h));
}
__device__ __forceinline__ void pack_hilo(float f0, float f1, uint32_t& ph, uint32_t& pl) {
    asm("cvt.rn.bf16x2.f32 %0, %1, %2;" : "=r"(ph) : "f"(f1), "f"(f0));
    float h0 = __uint_as_float(ph << 16);
    float h1 = __uint_as_float(ph & 0xFFFF0000u);
    float r0 = f0 - h0, r1 = f1 - h1;
    asm("cvt.rn.bf16x2.f32 %0, %1, %2;" : "=r"(pl) : "f"(r1), "f"(r0));
}
__device__ __forceinline__ void cp16(uint32_t dst, const void* src) {
    asm volatile("cp.async.cg.shared.global [%0], [%1], 16;" :: "r"(dst), "l"(src));
}
__device__ __forceinline__ void cp_commit() { asm volatile("cp.async.commit_group;"); }
template<int N> __device__ __forceinline__ void cp_wait() {
    asm volatile("cp.async.wait_group %0;" :: "n"(N));
}
#define LDSM4(r, addr) \
    asm volatile("ldmatrix.sync.aligned.m8n8.x4.shared.b16 {%0,%1,%2,%3}, [%4];" \
        : "=r"((r)[0]), "=r"((r)[1]), "=r"((r)[2]), "=r"((r)[3]) : "r"(addr))
#define MMA(d, a, b) \
    asm volatile("mma.sync.aligned.m16n8k16.row.col.f32.bf16.bf16.f32 " \
        "{%0,%1,%2,%3}, {%4,%5,%6,%7}, {%8,%9}, {%0,%1,%2,%3};" \
        : "+f"((d)[0]), "+f"((d)[1]), "+f"((d)[2]), "+f"((d)[3]) \
        : "r"((a)[0]), "r"((a)[1]), "r"((a)[2]), "r"((a)[3]), "r"((b)[0]), "r"((b)[1]))

// ---------------- generic 3-term bf16 GEMM core (2-stage) ----------------
template<int BM, int BN, int WGN, int WM, int BKt>
__device__ __forceinline__ void gemm_core(
    const __nv_bfloat16* __restrict__ Ahi, const __nv_bfloat16* __restrict__ Alo, int lda,
    const __nv_bfloat16* __restrict__ Bhi, const __nv_bfloat16* __restrict__ Blo, int ldb,
    int K, uint32_t sb, float* acc)
{
    constexpr int WNB = BN / WGN;
    constexpr int MT  = WM / 16;
    constexpr int NT  = WNB / 8;
    constexpr int PITCH = BKt * 2 + 16;
    constexpr int CPR = BKt / 8;
    constexpr int ABY = BM * PITCH;
    constexpr int BBY = BN * PITCH;
    constexpr int STG = 2 * ABY + 2 * BBY;

    const int tid = threadIdx.x;
    const int wid = tid >> 5, lane = tid & 31;
    const int wm = wid / WGN, wn = wid % WGN;

    auto issue = [&](int it, int buf) {
        const int k0 = it * BKt;
        const uint32_t base = sb + buf * STG;
        #pragma unroll
        for (int c = tid; c < BM * CPR; c += 256) {
            int row = c / CPR, seg = c % CPR;
            uint32_t d = base + row * PITCH + seg * 16;
            cp16(d,       Ahi + (size_t)row * lda + k0 + seg * 8);
            cp16(d + ABY, Alo + (size_t)row * lda + k0 + seg * 8);
        }
        #pragma unroll
        for (int c = tid; c < BN * CPR; c += 256) {
            int row = c / CPR, seg = c % CPR;
            uint32_t d = base + 2 * ABY + row * PITCH + seg * 16;
            cp16(d,       Bhi + (size_t)row * ldb + k0 + seg * 8);
            cp16(d + BBY, Blo + (size_t)row * ldb + k0 + seg * 8);
        }
        cp_commit();
    };

    auto compute = [&](int buf) {
        const uint32_t aB = sb + buf * STG +
            (uint32_t)((wm * WM + (lane & 15)) * PITCH + ((lane >> 4) << 4));
        const uint32_t bB = sb + buf * STG + 2 * ABY +
            (uint32_t)((wn * WNB + (lane & 7) + (((lane >> 4) & 1) << 3)) * PITCH +
                       (((lane >> 3) & 1) << 4));
        #pragma unroll
        for (int ks = 0; ks < BKt / 16; ks++) {
            uint32_t ah[MT][4], al[MT][4];
            #pragma unroll
            for (int mt = 0; mt < MT; mt++) {
                LDSM4(ah[mt], aB + mt * 16 * PITCH + ks * 32);
                LDSM4(al[mt], aB + ABY + mt * 16 * PITCH + ks * 32);
            }
            uint32_t bh[NT][2], bl[NT][2];
            #pragma unroll
            for (int np = 0; np < NT / 2; np++) {
                uint32_t t[4];
                LDSM4(t, bB + np * 16 * PITCH + ks * 32);
                bh[2*np][0] = t[0]; bh[2*np][1] = t[1];
                bh[2*np+1][0] = t[2]; bh[2*np+1][1] = t[3];
                LDSM4(t, bB + BBY + np * 16 * PITCH + ks * 32);
                bl[2*np][0] = t[0]; bl[2*np][1] = t[1];
                bl[2*np+1][0] = t[2]; bl[2*np+1][1] = t[3];
            }
            #pragma unroll
            for (int mt = 0; mt < MT; mt++)
                #pragma unroll
                for (int nt = 0; nt < NT; nt++) {
                    float* d = acc + (mt * NT + nt) * 4;
                    MMA(d, ah[mt], bh[nt]);
                    MMA(d, ah[mt], bl[nt]);
                    MMA(d, al[mt], bh[nt]);
                }
        }
    };

    const int niter = K / BKt;
    issue(0, 0);
    for (int it = 0; it < niter; it++) {
        if (it + 1 < niter) { issue(it + 1, (it + 1) & 1); cp_wait<1>(); }
        else                { cp_wait<0>(); }
        __syncthreads();
        compute(it & 1);
        __syncthreads();
    }
}

// ---------------- conversion kernels ----------------
__global__ void conv_x(const float* __restrict__ x) {
    int i = blockIdx.x * 256 + threadIdx.x;
    float4 v = reinterpret_cast<const float4*>(x)[i];
    uint32_t h01, l01, h23, l23;
    pack_hilo(v.x, v.y, h01, l01);
    pack_hilo(v.z, v.w, h23, l23);
    reinterpret_cast<uint32_t*>(g_xhi)[i * 2]     = h01;
    reinterpret_cast<uint32_t*>(g_xhi)[i * 2 + 1] = h23;
    reinterpret_cast<uint32_t*>(g_xlo)[i * 2]     = l01;
    reinterpret_cast<uint32_t*>(g_xlo)[i * 2 + 1] = l23;
}

__global__ void conv_w(const float* __restrict__ Wq, const float* __restrict__ Wk,
                       const float* __restrict__ Wv) {
    const float* W = (blockIdx.z == 0) ? Wq : (blockIdx.z == 1) ? Wk : Wv;
    __nv_bfloat16* dh = g_wthi + (size_t)blockIdx.z * Ec * Ec;
    __nv_bfloat16* dl = g_wtlo + (size_t)blockIdx.z * Ec * Ec;
    __shared__ float t[32][33];
    int tx = threadIdx.x, ty = threadIdx.y;
    int k0 = blockIdx.x * 32, n0 = blockIdx.y * 32;
    #pragma unroll
    for (int i = 0; i < 4; i++)
        t[ty + i * 8][tx] = W[(size_t)(k0 + ty + i * 8) * Ec + n0 + tx];
    __syncthreads();
    #pragma unroll
    for (int i = 0; i < 4; i++) {
        float v = t[tx][ty + i * 8];
        __nv_bfloat16 h, l; split_bf(v, h, l);
        size_t o = (size_t)(n0 + ty + i * 8) * Ec + k0 + tx;
        dh[o] = h; dl[o] = l;
    }
}

// ---------------- GEMM 1: QKV projection (128x128 tile) ----------------
__global__ void __launch_bounds__(256) k_proj_t(const float* __restrict__ bq,
                                                const float* __restrict__ bk,
                                                const float* __restrict__ bv) {
    extern __shared__ char smem[];
    uint32_t sb = smem_u32(smem);
    const int tid = threadIdx.x;
    const int z = blockIdx.z;
    const int n0 = blockIdx.x * 128, m0 = blockIdx.y * 128;
    const float* bias = (z == 0) ? bq : (z == 1) ? bk : bv;
    const __nv_bfloat16* Whi = g_wthi + (size_t)z * Ec * Ec;
    const __nv_bfloat16* Wlo = g_wtlo + (size_t)z * Ec * Ec;

    float acc[64] = {};
    gemm_core<128, 128, 4, 64, 32>(g_xhi + (size_t)m0 * Ec, g_xlo + (size_t)m0 * Ec, Ec,
                                   Whi + (size_t)n0 * Ec,   Wlo + (size_t)n0 * Ec,   Ec,
                                   Ec, sb, acc);

    float* stage = reinterpret_cast<float*>(smem);   // 128 x pitch130
    const int wid = tid >> 5, lane = tid & 31;
    const int wm = wid >> 2, wn = wid & 3;
    #pragma unroll
    for (int mt = 0; mt < 4; mt++)
        #pragma unroll
        for (int nt = 0; nt < 4; nt++) {
            int r0 = wm * 64 + mt * 16 + (lane >> 2);
            int c0 = wn * 32 + nt * 8 + (lane & 3) * 2;
            float* d = acc + (mt * 4 + nt) * 4;
            stage[r0 * 130 + c0] = d[0]; stage[r0 * 130 + c0 + 1] = d[1];
            stage[(r0 + 8) * 130 + c0] = d[2]; stage[(r0 + 8) * 130 + c0 + 1] = d[3];
        }
    __syncthreads();

    if (z < 2) {
        __nv_bfloat16* dh = (z == 0) ? g_qhi : g_khi;
        __nv_bfloat16* dl = (z == 0) ? g_qlo : g_klo;
        #pragma unroll
        for (int head = 0; head < 2; head++) {
            int h = (n0 >> 6) + head;
            for (int c = tid; c < 1024; c += 256) {
                int row = c >> 3, seg = c & 7;
                int m = m0 + row, b = m >> 11, l = m & 2047;
                uint32_t ph[4], pl[4];
                #pragma unroll
                for (int j = 0; j < 4; j++) {
                    float f0 = stage[row * 130 + head * 64 + seg * 8 + 2 * j] +
                               bias[n0 + head * 64 + seg * 8 + 2 * j];
                    float f1 = stage[row * 130 + head * 64 + seg * 8 + 2 * j + 1] +
                               bias[n0 + head * 64 + seg * 8 + 2 * j + 1];
                    pack_hilo(f0, f1, ph[j], pl[j]);
                }
                size_t o = ((size_t)(b * Hc + h) * Lc + l) * Dc + seg * 8;
                *reinterpret_cast<uint4*>(dh + o) = make_uint4(ph[0], ph[1], ph[2], ph[3]);
                *reinterpret_cast<uint4*>(dl + o) = make_uint4(pl[0], pl[1], pl[2], pl[3]);
            }
        }
    } else {
        for (int c = tid; c < 4096; c += 256) {
            int row = c >> 5, sg = c & 31;
            int head = sg >> 4, seg = sg & 15;
            int m = m0 + row, b = m >> 11, l = m & 2047;
            int h = (n0 >> 6) + head;
            float4 v;
            v.x = stage[row * 130 + head * 64 + seg * 4 + 0] + bias[n0 + head * 64 + seg * 4 + 0];
            v.y = stage[row * 130 + head * 64 + seg * 4 + 1] + bias[n0 + head * 64 + seg * 4 + 1];
            v.z = stage[row * 130 + head * 64 + seg * 4 + 2] + bias[n0 + head * 64 + seg * 4 + 2];
            v.w = stage[row * 130 + head * 64 + seg * 4 + 3] + bias[n0 + head * 64 + seg * 4 + 3];
            *reinterpret_cast<float4*>(g_v + ((size_t)(b * Hc + h) * Lc + l) * Dc + seg * 4) = v;
        }
    }
}

// ---------------- pass 1: scores colsums ONLY (no E store) ----------------
__global__ void __launch_bounds__(256) k_scores_s() {
    extern __shared__ char smem[];
    uint32_t sb = smem_u32(smem);
    const int tid = threadIdx.x;
    const int bh = blockIdx.z, m0 = blockIdx.x * 128, l0 = blockIdx.y * 128;

    float acc[64] = {};
    gemm_core<128, 128, 4, 64, 32>(g_qhi + ((size_t)bh * Lc + l0) * Dc,
                                   g_qlo + ((size_t)bh * Lc + l0) * Dc, Dc,
                                   g_khi + ((size_t)bh * Lc + m0) * Dc,
                                   g_klo + ((size_t)bh * Lc + m0) * Dc, Dc,
                                   Dc, sb, acc);

    float* colp = reinterpret_cast<float*>(smem);    // [2][128]
    const int lane = tid & 31;
    const int wn = (tid >> 5) & 3, wm = tid >> 7;

    float cs[4][2] = {};
    #pragma unroll
    for (int mt = 0; mt < 4; mt++)
        #pragma unroll
        for (int nt = 0; nt < 4; nt++) {
            float* d = acc + (mt * 4 + nt) * 4;
            cs[nt][0] += __expf(d[0]) + __expf(d[2]);
            cs[nt][1] += __expf(d[1]) + __expf(d[3]);
        }
    #pragma unroll
    for (int nt = 0; nt < 4; nt++)
        #pragma unroll
        for (int p = 0; p < 2; p++) {
            float v = cs[nt][p];
            v += __shfl_xor_sync(0xffffffffu, v, 4);
            v += __shfl_xor_sync(0xffffffffu, v, 8);
            v += __shfl_xor_sync(0xffffffffu, v, 16);
            cs[nt][p] = v;
        }
    if (lane < 4) {
        #pragma unroll
        for (int nt = 0; nt < 4; nt++) {
            int cp = wn * 16 + nt * 4 + lane;
            colp[wm * 128 + cp * 2]     = cs[nt][0];
            colp[wm * 128 + cp * 2 + 1] = cs[nt][1];
        }
    }
    __syncthreads();
    if (tid < 128)
        g_psum[((size_t)bh * 16 + blockIdx.y) * Lc + m0 + tid] = colp[tid] + colp[128 + tid];
}

// ---------------- Vs^T = (V * dinv)^T as bf16 hi/lo (dinv fused) ----------------
__global__ void k_vscale() {
    __shared__ float tv[64][65];
    __shared__ float dsm[64];
    int tid = threadIdx.x;
    int bh = blockIdx.y, m0 = blockIdx.x * 64;
    if (tid < 64) {
        float s = 0.0f;
        #pragma unroll
        for (int j = 0; j < 16; j++) s += g_psum[((size_t)bh * 16 + j) * Lc + m0 + tid];
        dsm[tid] = 1.0f / s;
    }
    __syncthreads();
    const float* V = g_v + ((size_t)bh * Lc + m0) * Dc;
    #pragma unroll
    for (int i = 0; i < 16; i++) {
        int e = tid + i * 256;
        int r = e >> 6, d = e & 63;
        tv[r][d] = V[r * Dc + d] * dsm[r];
    }
    __syncthreads();
    #pragma unroll
    for (int i = 0; i < 16; i++) {
        int e = tid + i * 256;
        int d = e >> 6, c = e & 63;
        float v = tv[c][d];
        __nv_bfloat16 h, l; split_bf(v, h, l);
        size_t o = ((size_t)bh * Dc + d) * Lc + m0 + c;
        g_vthi[o] = h; g_vtlo[o] = l;
    }
}

// ---------------- pass 2: fused recompute-S + PV ----------------
// per CTA: 128 l-rows x 64 d. Warp w owns l-rows [w*16, w*16+16).
// smem: Q [128][144] hi + lo (36864); 2 stages x {Khi,Klo,Vth,Vtl} 64x144 each (36864/stage)
constexpr int FP_PITCH = 144;
constexpr int FP_QLO   = 128 * FP_PITCH;            // 18432
constexpr int FP_STAGE = 2 * FP_QLO;                // 36864 (stage0 base)
constexpr int FP_SSZ   = 4 * 64 * FP_PITCH;         // 36864 per stage
constexpr int FP_SMEM  = FP_STAGE + 2 * FP_SSZ;     // 110592

__global__ void __launch_bounds__(256) k_fused_pv(float* __restrict__ outF) {
    extern __shared__ char smem[];
    uint32_t sb = smem_u32(smem);
    const int tid = threadIdx.x;
    const int wid = tid >> 5, lane = tid & 31;
    const int bh = blockIdx.y, b = bh >> 4, h = bh & 15;
    const int l0 = blockIdx.x * 128;

    const __nv_bfloat16* Qh = g_qhi + ((size_t)bh * Lc + l0) * Dc;
    const __nv_bfloat16* Ql = g_qlo + ((size_t)bh * Lc + l0) * Dc;
    const __nv_bfloat16* Kh = g_khi + (size_t)bh * Lc * Dc;
    const __nv_bfloat16* Kl = g_klo + (size_t)bh * Lc * Dc;
    const __nv_bfloat16* Vh = g_vthi + (size_t)bh * Dc * Lc;
    const __nv_bfloat16* Vl = g_vtlo + (size_t)bh * Dc * Lc;

    // Q load (joins stage-0 commit group)
    #pragma unroll
    for (int c = tid; c < 1024; c += 256) {       // 128 rows x 8 segs
        int row = c >> 3, seg = c & 7;
        uint32_t d = sb + row * FP_PITCH + seg * 16;
        cp16(d,          Qh + (size_t)row * Dc + seg * 8);
        cp16(d + FP_QLO, Ql + (size_t)row * Dc + seg * 8);
    }

    auto issue = [&](int chunk, int buf) {
        const int mc = chunk * 64;
        const uint32_t base = sb + FP_STAGE + buf * FP_SSZ;
        #pragma unroll
        for (int c = tid; c < 512; c += 256) {    // 64 rows x 8 segs
            int row = c >> 3, seg = c & 7;
            uint32_t d = base + row * FP_PITCH + seg * 16;
            cp16(d,              Kh + (size_t)(mc + row) * Dc + seg * 8);
            cp16(d + 9216,       Kl + (size_t)(mc + row) * Dc + seg * 8);
            cp16(d + 18432,      Vh + (size_t)row * Lc + mc + seg * 8);
            cp16(d + 27648,      Vl + (size_t)row * Lc + mc + seg * 8);
        }
        cp_commit();
    };

    float out[32] = {};
    const uint32_t aQ = sb + (uint32_t)((wid * 16 + (lane & 15)) * FP_PITCH + ((lane >> 4) << 4));
    const uint32_t bPat = (uint32_t)(((lane & 7) + (((lane >> 4) & 1) << 3)) * FP_PITCH +
                                     (((lane >> 3) & 1) << 4));

    issue(0, 0);
    for (int it = 0; it < 32; it++) {
        if (it + 1 < 32) { issue(it + 1, (it + 1) & 1); cp_wait<1>(); }
        else             { cp_wait<0>(); }
        __syncthreads();

        const uint32_t kst = sb + FP_STAGE + (it & 1) * FP_SSZ;
        // ---- S = Q K^T (3-term), acc fp32 ----
        float s[32] = {};
        #pragma unroll
        for (int ks = 0; ks < 4; ks++) {
            uint32_t qh[4], ql[4];
            LDSM4(qh, aQ + ks * 32);
            LDSM4(ql, aQ + FP_QLO + ks * 32);
            uint32_t kh[8][2], kl[8][2];
            #pragma unroll
            for (int np = 0; np < 4; np++) {
                uint32_t t[4];
                LDSM4(t, kst + np * 16 * FP_PITCH + bPat + ks * 32);
                kh[2*np][0] = t[0]; kh[2*np][1] = t[1];
                kh[2*np+1][0] = t[2]; kh[2*np+1][1] = t[3];
                LDSM4(t, kst + 9216 + np * 16 * FP_PITCH + bPat + ks * 32);
                kl[2*np][0] = t[0]; kl[2*np][1] = t[1];
                kl[2*np+1][0] = t[2]; kl[2*np+1][1] = t[3];
            }
            #pragma unroll
            for (int nt = 0; nt < 8; nt++) {
                float* d = s + nt * 4;
                MMA(d, qh, kh[nt]);
                MMA(d, qh, kl[nt]);
                MMA(d, ql, kh[nt]);
            }
        }
        // ---- E = exp(S), pack to A-frags (C-frag == A-frag identity) ----
        uint32_t ehp[16], elp[16];
        #pragma unroll
        for (int nt = 0; nt < 8; nt++) {
            float e0 = __expf(s[nt*4+0]), e1 = __expf(s[nt*4+1]);
            float e2 = __expf(s[nt*4+2]), e3 = __expf(s[nt*4+3]);
            pack_hilo(e0, e1, ehp[2*nt],   elp[2*nt]);
            pack_hilo(e2, e3, ehp[2*nt+1], elp[2*nt+1]);
        }
        // ---- out += E * Vt (3-term) ----
        const uint32_t vst = kst + 18432;
        #pragma unroll
        for (int kc = 0; kc < 4; kc++) {
            uint32_t vh[8][2], vl[8][2];
            #pragma unroll
            for (int np = 0; np < 4; np++) {
                uint32_t t[4];
                LDSM4(t, vst + np * 16 * FP_PITCH + bPat + kc * 32);
                vh[2*np][0] = t[0]; vh[2*np][1] = t[1];
                vh[2*np+1][0] = t[2]; vh[2*np+1][1] = t[3];
                LDSM4(t, vst + 9216 + np * 16 * FP_PITCH + bPat + kc * 32);
                vl[2*np][0] = t[0]; vl[2*np][1] = t[1];
                vl[2*np+1][0] = t[2]; vl[2*np+1][1] = t[3];
            }
            const uint32_t* ah = &ehp[4*kc];
            const uint32_t* al = &elp[4*kc];
            #pragma unroll
            for (int nt = 0; nt < 8; nt++) {
                float* d = out + nt * 4;
                MMA(d, ah, vh[nt]);
                MMA(d, ah, vl[nt]);
                MMA(d, al, vh[nt]);
            }
        }
        __syncthreads();
    }

    // epilogue: stage + coalesced write
    float* stage = reinterpret_cast<float*>(smem);     // 128 x pitch68
    #pragma unroll
    for (int nt = 0; nt < 8; nt++) {
        int r0 = wid * 16 + (lane >> 2);
        int c0 = nt * 8 + (lane & 3) * 2;
        float* d = out + nt * 4;
        stage[r0 * 68 + c0] = d[0]; stage[r0 * 68 + c0 + 1] = d[1];
        stage[(r0 + 8) * 68 + c0] = d[2]; stage[(r0 + 8) * 68 + c0 + 1] = d[3];
    }
    __syncthreads();
    for (int c = tid; c < 2048; c += 256) {            // 128 rows x 16 float4
        int row = c >> 4, seg = c & 15;
        float4 v = *reinterpret_cast<float4*>(&stage[row * 68 + seg * 4]);
        *reinterpret_cast<float4*>(outF + ((size_t)b * Lc + l0 + row) * Ec + h * Dc + seg * 4) = v;
    }
}

// ---------------- launch ----------------
extern "C" void kernel_launch(void* const* d_in, const int* in_sizes, int n_in,
                              void* d_out, int out_size) {
    const float* x  = (const float*)d_in[0];
    const float* Wq = (const float*)d_in[1];
    const float* bq = (const float*)d_in[2];
    const float* Wk = (const float*)d_in[3];
    const float* bk = (const float*)d_in[4];
    const float* Wv = (const float*)d_in[5];
    const float* bv = (const float*)d_in[6];
    float* out = (float*)d_out;

    cudaFuncSetAttribute(k_proj_t,   cudaFuncAttributeMaxDynamicSharedMemorySize, 81920);
    cudaFuncSetAttribute(k_scores_s, cudaFuncAttributeMaxDynamicSharedMemorySize, 81920);
    cudaFuncSetAttribute(k_fused_pv, cudaFuncAttributeMaxDynamicSharedMemorySize, FP_SMEM);

    conv_x<<<Mr * Ec / 1024, 256>>>(x);
    conv_w<<<dim3(32, 32, 3), dim3(32, 8)>>>(Wq, Wk, Wv);
    k_proj_t<<<dim3(8, 32, 3), 256, 81920>>>(bq, bk, bv);
    k_scores_s<<<dim3(16, 16, 32), 256, 81920>>>();
    k_vscale<<<dim3(32, 32), 256>>>();
    k_fused_pv<<<dim3(16, 32), 256, FP_SMEM>>>(out);
}

// round 12
// speedup vs baseline: 1.0830x; 1.0425x over previous
#include <cuda_runtime.h>
#include <cuda_bf16.h>
#include <cstdint>

// ---------------- problem constants ----------------
constexpr int Lc = 2048, Ec = 1024, Hc = 16, Dc = 64, Bc = 2;
constexpr int BHc = Bc * Hc;     // 32
constexpr int Mr  = Bc * Lc;     // 4096
constexpr float LOG2E = 1.4426950408889634f;

// ---------------- device scratch ----------------
__device__ __nv_bfloat16 g_xhi[Mr * Ec],  g_xlo[Mr * Ec];
__device__ __nv_bfloat16 g_wthi[3 * Ec * Ec], g_wtlo[3 * Ec * Ec];
__device__ __nv_bfloat16 g_qhi[BHc * Lc * Dc], g_qlo[BHc * Lc * Dc];   // pre-scaled by log2e
__device__ __nv_bfloat16 g_khi[BHc * Lc * Dc], g_klo[BHc * Lc * Dc];
__device__ float         g_v  [BHc * Lc * Dc];
__device__ __nv_bfloat16 g_vthi[BHc * Dc * Lc], g_vtlo[BHc * Dc * Lc];
__device__ __nv_bfloat16 g_ehi[(size_t)BHc * Lc * Lc];   // 268MB
__device__ __nv_bfloat16 g_elo[(size_t)BHc * Lc * Lc];   // 268MB
__device__ float         g_psum[(size_t)BHc * 16 * Lc];

// ---------------- helpers ----------------
__device__ __forceinline__ uint32_t smem_u32(const void* p) {
    uint32_t a;
    asm("{ .reg .u64 t; cvta.to.shared.u64 t, %1; cvt.u32.u64 %0, t; }" : "=r"(a) : "l"(p));
    return a;
}
__device__ __forceinline__ void split_bf(float f, __nv_bfloat16& h, __nv_bfloat16& l) {
    h = __float2bfloat16(f);
    l = __float2bfloat16(f - __bfloat162float(h));
}
__device__ __forceinline__ void pack_hilo(float f0, float f1, uint32_t& ph, uint32_t& pl) {
    asm("cvt.rn.bf16x2.f32 %0, %1, %2;" : "=r"(ph) : "f"(f1), "f"(f0));
    float h0 = __uint_as_float(ph << 16);
    float h1 = __uint_as_float(ph & 0xFFFF0000u);
    float r0 = f0 - h0, r1 = f1 - h1;
    asm("cvt.rn.bf16x2.f32 %0, %1, %2;" : "=r"(pl) : "f"(r1), "f"(r0));
}
__device__ __forceinline__ void cp16(uint32_t dst, const void* src) {
    asm volatile("cp.async.cg.shared.global [%0], [%1], 16;" :: "r"(dst), "l"(src));
}
__device__ __forceinline__ void cp_commit() { asm volatile("cp.async.commit_group;"); }
template<int N> __device__ __forceinline__ void cp_wait() {
    asm volatile("cp.async.wait_group %0;" :: "n"(N));
}
#define LDSM4(r, addr) \
    asm volatile("ldmatrix.sync.aligned.m8n8.x4.shared.b16 {%0,%1,%2,%3}, [%4];" \
        : "=r"((r)[0]), "=r"((r)[1]), "=r"((r)[2]), "=r"((r)[3]) : "r"(addr))
#define MMA(d, a, b) \
    asm volatile("mma.sync.aligned.m16n8k16.row.col.f32.bf16.bf16.f32 " \
        "{%0,%1,%2,%3}, {%4,%5,%6,%7}, {%8,%9}, {%0,%1,%2,%3};" \
        : "+f"((d)[0]), "+f"((d)[1]), "+f"((d)[2]), "+f"((d)[3]) \
        : "r"((a)[0]), "r"((a)[1]), "r"((a)[2]), "r"((a)[3]), "r"((b)[0]), "r"((b)[1]))

// ---------------- generic 3-term bf16 GEMM core (2-stage) ----------------
template<int BM, int BN, int WGN, int WM, int BKt>
__device__ __forceinline__ void gemm_core(
    const __nv_bfloat16* __restrict__ Ahi, const __nv_bfloat16* __restrict__ Alo, int lda,
    const __nv_bfloat16* __restrict__ Bhi, const __nv_bfloat16* __restrict__ Blo, int ldb,
    int K, uint32_t sb, float* acc)
{
    constexpr int WNB = BN / WGN;
    constexpr int MT  = WM / 16;
    constexpr int NT  = WNB / 8;
    constexpr int PITCH = BKt * 2 + 16;
    constexpr int CPR = BKt / 8;
    constexpr int ABY = BM * PITCH;
    constexpr int BBY = BN * PITCH;
    constexpr int STG = 2 * ABY + 2 * BBY;

    const int tid = threadIdx.x;
    const int wid = tid >> 5, lane = tid & 31;
    const int wm = wid / WGN, wn = wid % WGN;

    auto issue = [&](int it, int buf) {
        const int k0 = it * BKt;
        const uint32_t base = sb + buf * STG;
        #pragma unroll
        for (int c = tid; c < BM * CPR; c += 256) {
            int row = c / CPR, seg = c % CPR;
            uint32_t d = base + row * PITCH + seg * 16;
            cp16(d,       Ahi + (size_t)row * lda + k0 + seg * 8);
            cp16(d + ABY, Alo + (size_t)row * lda + k0 + seg * 8);
        }
        #pragma unroll
        for (int c = tid; c < BN * CPR; c += 256) {
            int row = c / CPR, seg = c % CPR;
            uint32_t d = base + 2 * ABY + row * PITCH + seg * 16;
            cp16(d,       Bhi + (size_t)row * ldb + k0 + seg * 8);
            cp16(d + BBY, Blo + (size_t)row * ldb + k0 + seg * 8);
        }
        cp_commit();
    };

    auto compute = [&](int buf) {
        const uint32_t aB = sb + buf * STG +
            (uint32_t)((wm * WM + (lane & 15)) * PITCH + ((lane >> 4) << 4));
        const uint32_t bB = sb + buf * STG + 2 * ABY +
            (uint32_t)((wn * WNB + (lane & 7) + (((lane >> 4) & 1) << 3)) * PITCH +
                       (((lane >> 3) & 1) << 4));
        #pragma unroll
        for (int ks = 0; ks < BKt / 16; ks++) {
            uint32_t ah[MT][4], al[MT][4];
            #pragma unroll
            for (int mt = 0; mt < MT; mt++) {
                LDSM4(ah[mt], aB + mt * 16 * PITCH + ks * 32);
                LDSM4(al[mt], aB + ABY + mt * 16 * PITCH + ks * 32);
            }
            uint32_t bh[NT][2], bl[NT][2];
            #pragma unroll
            for (int np = 0; np < NT / 2; np++) {
                uint32_t t[4];
                LDSM4(t, bB + np * 16 * PITCH + ks * 32);
                bh[2*np][0] = t[0]; bh[2*np][1] = t[1];
                bh[2*np+1][0] = t[2]; bh[2*np+1][1] = t[3];
                LDSM4(t, bB + BBY + np * 16 * PITCH + ks * 32);
                bl[2*np][0] = t[0]; bl[2*np][1] = t[1];
                bl[2*np+1][0] = t[2]; bl[2*np+1][1] = t[3];
            }
            #pragma unroll
            for (int mt = 0; mt < MT; mt++)
                #pragma unroll
                for (int nt = 0; nt < NT; nt++) {
                    float* d = acc + (mt * NT + nt) * 4;
                    MMA(d, ah[mt], bh[nt]);
                    MMA(d, ah[mt], bl[nt]);
                    MMA(d, al[mt], bh[nt]);
                }
        }
    };

    const int niter = K / BKt;
    issue(0, 0);
    for (int it = 0; it < niter; it++) {
        if (it + 1 < niter) { issue(it + 1, (it + 1) & 1); cp_wait<1>(); }
        else                { cp_wait<0>(); }
        __syncthreads();
        compute(it & 1);
        __syncthreads();
    }
}

// ---------------- conversion kernels ----------------
__global__ void conv_x(const float* __restrict__ x) {
    int i = blockIdx.x * 256 + threadIdx.x;
    float4 v = reinterpret_cast<const float4*>(x)[i];
    uint32_t h01, l01, h23, l23;
    pack_hilo(v.x, v.y, h01, l01);
    pack_hilo(v.z, v.w, h23, l23);
    reinterpret_cast<uint32_t*>(g_xhi)[i * 2]     = h01;
    reinterpret_cast<uint32_t*>(g_xhi)[i * 2 + 1] = h23;
    reinterpret_cast<uint32_t*>(g_xlo)[i * 2]     = l01;
    reinterpret_cast<uint32_t*>(g_xlo)[i * 2 + 1] = l23;
}

__global__ void conv_w(const float* __restrict__ Wq, const float* __restrict__ Wk,
                       const float* __restrict__ Wv) {
    const float* W = (blockIdx.z == 0) ? Wq : (blockIdx.z == 1) ? Wk : Wv;
    __nv_bfloat16* dh = g_wthi + (size_t)blockIdx.z * Ec * Ec;
    __nv_bfloat16* dl = g_wtlo + (size_t)blockIdx.z * Ec * Ec;
    __shared__ float t[32][33];
    int tx = threadIdx.x, ty = threadIdx.y;
    int k0 = blockIdx.x * 32, n0 = blockIdx.y * 32;
    #pragma unroll
    for (int i = 0; i < 4; i++)
        t[ty + i * 8][tx] = W[(size_t)(k0 + ty + i * 8) * Ec + n0 + tx];
    __syncthreads();
    #pragma unroll
    for (int i = 0; i < 4; i++) {
        float v = t[tx][ty + i * 8];
        __nv_bfloat16 h, l; split_bf(v, h, l);
        size_t o = (size_t)(n0 + ty + i * 8) * Ec + k0 + tx;
        dh[o] = h; dl[o] = l;
    }
}

// ---------------- GEMM 1: QKV projection (128x128 tile) ----------------
__global__ void __launch_bounds__(256) k_proj_t(const float* __restrict__ bq,
                                                const float* __restrict__ bk,
                                                const float* __restrict__ bv) {
    extern __shared__ char smem[];
    uint32_t sb = smem_u32(smem);
    const int tid = threadIdx.x;
    const int z = blockIdx.z;
    const int n0 = blockIdx.x * 128, m0 = blockIdx.y * 128;
    const float* bias = (z == 0) ? bq : (z == 1) ? bk : bv;
    const __nv_bfloat16* Whi = g_wthi + (size_t)z * Ec * Ec;
    const __nv_bfloat16* Wlo = g_wtlo + (size_t)z * Ec * Ec;
    const float scl = (z == 0) ? LOG2E : 1.0f;

    float acc[64] = {};
    gemm_core<128, 128, 4, 64, 32>(g_xhi + (size_t)m0 * Ec, g_xlo + (size_t)m0 * Ec, Ec,
                                   Whi + (size_t)n0 * Ec,   Wlo + (size_t)n0 * Ec,   Ec,
                                   Ec, sb, acc);

    float* stage = reinterpret_cast<float*>(smem);   // 128 x pitch130
    const int wid = tid >> 5, lane = tid & 31;
    const int wm = wid >> 2, wn = wid & 3;
    #pragma unroll
    for (int mt = 0; mt < 4; mt++)
        #pragma unroll
        for (int nt = 0; nt < 4; nt++) {
            int r0 = wm * 64 + mt * 16 + (lane >> 2);
            int c0 = wn * 32 + nt * 8 + (lane & 3) * 2;
            float* d = acc + (mt * 4 + nt) * 4;
            stage[r0 * 130 + c0] = d[0]; stage[r0 * 130 + c0 + 1] = d[1];
            stage[(r0 + 8) * 130 + c0] = d[2]; stage[(r0 + 8) * 130 + c0 + 1] = d[3];
        }
    __syncthreads();

    if (z < 2) {
        __nv_bfloat16* dh = (z == 0) ? g_qhi : g_khi;
        __nv_bfloat16* dl = (z == 0) ? g_qlo : g_klo;
        #pragma unroll
        for (int head = 0; head < 2; head++) {
            int h = (n0 >> 6) + head;
            for (int c = tid; c < 1024; c += 256) {
                int row = c >> 3, seg = c & 7;
                int m = m0 + row, b = m >> 11, l = m & 2047;
                uint32_t ph[4], pl[4];
                #pragma unroll
                for (int j = 0; j < 4; j++) {
                    float f0 = (stage[row * 130 + head * 64 + seg * 8 + 2 * j] +
                                bias[n0 + head * 64 + seg * 8 + 2 * j]) * scl;
                    float f1 = (stage[row * 130 + head * 64 + seg * 8 + 2 * j + 1] +
                                bias[n0 + head * 64 + seg * 8 + 2 * j + 1]) * scl;
                    pack_hilo(f0, f1, ph[j], pl[j]);
                }
                size_t o = ((size_t)(b * Hc + h) * Lc + l) * Dc + seg * 8;
                *reinterpret_cast<uint4*>(dh + o) = make_uint4(ph[0], ph[1], ph[2], ph[3]);
                *reinterpret_cast<uint4*>(dl + o) = make_uint4(pl[0], pl[1], pl[2], pl[3]);
            }
        }
    } else {
        for (int c = tid; c < 4096; c += 256) {
            int row = c >> 5, sg = c & 31;
            int head = sg >> 4, seg = sg & 15;
            int m = m0 + row, b = m >> 11, l = m & 2047;
            int h = (n0 >> 6) + head;
            float4 v;
            v.x = stage[row * 130 + head * 64 + seg * 4 + 0] + bias[n0 + head * 64 + seg * 4 + 0];
            v.y = stage[row * 130 + head * 64 + seg * 4 + 1] + bias[n0 + head * 64 + seg * 4 + 1];
            v.z = stage[row * 130 + head * 64 + seg * 4 + 2] + bias[n0 + head * 64 + seg * 4 + 2];
            v.w = stage[row * 130 + head * 64 + seg * 4 + 3] + bias[n0 + head * 64 + seg * 4 + 3];
            *reinterpret_cast<float4*>(g_v + ((size_t)(b * Hc + h) * Lc + l) * Dc + seg * 4) = v;
        }
    }
}

// ---------------- GEMM 2: persistent scores + exp2 + colsums + E store ----------------
constexpr int SC_STG   = 40960;               // per-stage bytes (Ahi|Alo|Bhi|Blo x 10240)
constexpr int SC_ABY   = 10240;
constexpr int SC_SMEM  = 111616;
constexpr int SC_NT    = 16 * 16 * BHc;       // 8192 tiles
constexpr int SC_GRID  = 296;

__global__ void __launch_bounds__(256, 2) k_scores_p() {
    extern __shared__ char smem[];
    uint32_t sb = smem_u32(smem);
    const int tid = threadIdx.x;
    const int wid = tid >> 5, lane = tid & 31;
    const int wm = wid >> 2, wn = wid & 3;

    uint32_t* stH = reinterpret_cast<uint32_t*>(smem + 40960);     // [128][68]
    uint32_t* stL = reinterpret_cast<uint32_t*>(smem + 75776);     // [128][68]
    float* colp   = reinterpret_cast<float*>(smem + 110592);       // [2][128]

    auto issue = [&](int t, int kc, int buf) {
        const int mi = t & 15, li = (t >> 4) & 15, bh = t >> 8;
        const __nv_bfloat16* Ahi = g_qhi + ((size_t)bh * Lc + li * 128) * Dc + kc * 32;
        const __nv_bfloat16* Alo = g_qlo + ((size_t)bh * Lc + li * 128) * Dc + kc * 32;
        const __nv_bfloat16* Bhi = g_khi + ((size_t)bh * Lc + mi * 128) * Dc + kc * 32;
        const __nv_bfloat16* Blo = g_klo + ((size_t)bh * Lc + mi * 128) * Dc + kc * 32;
        const uint32_t base = sb + buf * SC_STG;
        #pragma unroll
        for (int c = tid; c < 512; c += 256) {
            int row = c >> 2, seg = c & 3;
            uint32_t d = base + row * 80 + seg * 16;
            cp16(d,            Ahi + (size_t)row * Dc + seg * 8);
            cp16(d + SC_ABY,   Alo + (size_t)row * Dc + seg * 8);
            cp16(d + 2*SC_ABY, Bhi + (size_t)row * Dc + seg * 8);
            cp16(d + 3*SC_ABY, Blo + (size_t)row * Dc + seg * 8);
        }
        cp_commit();
    };

    auto compute = [&](int buf, float* acc) {
        const uint32_t aB = sb + buf * SC_STG +
            (uint32_t)((wm * 64 + (lane & 15)) * 80 + ((lane >> 4) << 4));
        const uint32_t bB = sb + buf * SC_STG + 2 * SC_ABY +
            (uint32_t)((wn * 32 + (lane & 7) + (((lane >> 4) & 1) << 3)) * 80 +
                       (((lane >> 3) & 1) << 4));
        #pragma unroll
        for (int ks = 0; ks < 2; ks++) {
            uint32_t ah[4][4], al[4][4];
            #pragma unroll
            for (int mt = 0; mt < 4; mt++) {
                LDSM4(ah[mt], aB + mt * 16 * 80 + ks * 32);
                LDSM4(al[mt], aB + SC_ABY + mt * 16 * 80 + ks * 32);
            }
            uint32_t bh[4][2], bl[4][2];
            #pragma unroll
            for (int np = 0; np < 2; np++) {
                uint32_t t4[4];
                LDSM4(t4, bB + np * 16 * 80 + ks * 32);
                bh[2*np][0] = t4[0]; bh[2*np][1] = t4[1];
                bh[2*np+1][0] = t4[2]; bh[2*np+1][1] = t4[3];
                LDSM4(t4, bB + SC_ABY + np * 16 * 80 + ks * 32);
                bl[2*np][0] = t4[0]; bl[2*np][1] = t4[1];
                bl[2*np+1][0] = t4[2]; bl[2*np+1][1] = t4[3];
            }
            #pragma unroll
            for (int mt = 0; mt < 4; mt++)
                #pragma unroll
                for (int nt = 0; nt < 4; nt++) {
                    float* d = acc + (mt * 4 + nt) * 4;
                    MMA(d, ah[mt], bh[nt]);
                    MMA(d, ah[mt], bl[nt]);
                    MMA(d, al[mt], bh[nt]);
                }
        }
    };

    int t = blockIdx.x;
    if (t < SC_NT) issue(t, 0, 0);
    for (; t < SC_NT; t += SC_GRID) {
        const int mi = t & 15, li = (t >> 4) & 15, bh = t >> 8;
        const int m0 = mi * 128, l0 = li * 128;

        float acc[64] = {};
        issue(t, 1, 1);
        cp_wait<1>();
        __syncthreads();
        compute(0, acc);
        __syncthreads();               // FIX: all warps done reading buf0 before refill
        const int tn = t + SC_GRID;
        if (tn < SC_NT) { issue(tn, 0, 0); cp_wait<1>(); }
        else            { cp_wait<0>(); }
        __syncthreads();
        compute(1, acc);
        __syncthreads();               // all warps done reading buf1 before stage writes

        // epilogue: exp2 + colsums + pack into stage (overlaps b1)
        float cs[4][2] = {};
        #pragma unroll
        for (int mt = 0; mt < 4; mt++)
            #pragma unroll
            for (int nt = 0; nt < 4; nt++) {
                float* d = acc + (mt * 4 + nt) * 4;
                int r0 = wm * 64 + mt * 16 + (lane >> 2);
                int cp = wn * 16 + nt * 4 + (lane & 3);
                float e0 = exp2f(d[0]), e1 = exp2f(d[1]);
                float e2 = exp2f(d[2]), e3 = exp2f(d[3]);
                cs[nt][0] += e0 + e2;
                cs[nt][1] += e1 + e3;
                uint32_t ph, pl;
                pack_hilo(e0, e1, ph, pl);
                stH[r0 * 68 + cp] = ph; stL[r0 * 68 + cp] = pl;
                pack_hilo(e2, e3, ph, pl);
                stH[(r0 + 8) * 68 + cp] = ph; stL[(r0 + 8) * 68 + cp] = pl;
            }
        #pragma unroll
        for (int nt = 0; nt < 4; nt++)
            #pragma unroll
            for (int p = 0; p < 2; p++) {
                float v = cs[nt][p];
                v += __shfl_xor_sync(0xffffffffu, v, 4);
                v += __shfl_xor_sync(0xffffffffu, v, 8);
                v += __shfl_xor_sync(0xffffffffu, v, 16);
                cs[nt][p] = v;
            }
        if (lane < 4) {
            #pragma unroll
            for (int nt = 0; nt < 4; nt++) {
                int cp = wn * 16 + nt * 4 + lane;
                colp[wm * 128 + cp * 2]     = cs[nt][0];
                colp[wm * 128 + cp * 2 + 1] = cs[nt][1];
            }
        }
        __syncthreads();
        if (tid < 128)
            g_psum[((size_t)bh * 16 + li) * Lc + m0 + tid] = colp[tid] + colp[128 + tid];
        for (int c = tid; c < 2048; c += 256) {      // 128 rows x 16 uint4
            int row = c >> 4, seg = c & 15;
            size_t o = ((size_t)bh * Lc + l0 + row) * Lc + m0 + seg * 8;
            *reinterpret_cast<uint4*>(g_ehi + o) =
                *reinterpret_cast<uint4*>(&stH[row * 68 + seg * 4]);
            *reinterpret_cast<uint4*>(g_elo + o) =
                *reinterpret_cast<uint4*>(&stL[row * 68 + seg * 4]);
        }
        __syncthreads();   // stage reads done before next iter's b1 cp.async
    }
}

// ---------------- Vs^T = (V * dinv)^T as bf16 hi/lo (dinv fused) ----------------
__global__ void k_vscale() {
    __shared__ float tv[64][65];
    __shared__ float dsm[64];
    int tid = threadIdx.x;
    int bh = blockIdx.y, m0 = blockIdx.x * 64;
    if (tid < 64) {
        float s = 0.0f;
        #pragma unroll
        for (int j = 0; j < 16; j++) s += g_psum[((size_t)bh * 16 + j) * Lc + m0 + tid];
        dsm[tid] = 1.0f / s;
    }
    __syncthreads();
    const float* V = g_v + ((size_t)bh * Lc + m0) * Dc;
    #pragma unroll
    for (int i = 0; i < 16; i++) {
        int e = tid + i * 256;
        int r = e >> 6, d = e & 63;
        tv[r][d] = V[r * Dc + d] * dsm[r];
    }
    __syncthreads();
    #pragma unroll
    for (int i = 0; i < 16; i++) {
        int e = tid + i * 256;
        int d = e >> 6, c = e & 63;
        float v = tv[c][d];
        __nv_bfloat16 h, l; split_bf(v, h, l);
        size_t o = ((size_t)bh * Dc + d) * Lc + m0 + c;
        g_vthi[o] = h; g_vtlo[o] = l;
    }
}

// ---------------- GEMM 3: out = E * Vs^T (128x64, BK=64) ----------------
__global__ void __launch_bounds__(256) k_pv_t(float* __restrict__ outF) {
    extern __shared__ char smem[];
    uint32_t sb = smem_u32(smem);
    const int tid = threadIdx.x;
    const int bh = blockIdx.y, b = bh >> 4, h = bh & 15;
    const int l0 = blockIdx.x * 128;

    float acc[32] = {};
    gemm_core<128, 64, 2, 32, 64>(g_ehi + ((size_t)bh * Lc + l0) * Lc,
                                  g_elo + ((size_t)bh * Lc + l0) * Lc, Lc,
                                  g_vthi + (size_t)bh * Dc * Lc,
                                  g_vtlo + (size_t)bh * Dc * Lc,       Lc,
                                  Lc, sb, acc);

    float* stage = reinterpret_cast<float*>(smem);     // 128 x pitch68
    const int wid = tid >> 5, lane = tid & 31;
    const int wm = wid >> 1, wn = wid & 1;
    #pragma unroll
    for (int mt = 0; mt < 2; mt++)
        #pragma unroll
        for (int nt = 0; nt < 4; nt++) {
            int r0 = wm * 32 + mt * 16 + (lane >> 2);
            int c0 = wn * 32 + nt * 8 + (lane & 3) * 2;
            float* d = acc + (mt * 4 + nt) * 4;
            stage[r0 * 68 + c0] = d[0]; stage[r0 * 68 + c0 + 1] = d[1];
            stage[(r0 + 8) * 68 + c0] = d[2]; stage[(r0 + 8) * 68 + c0 + 1] = d[3];
        }
    __syncthreads();
    for (int c = tid; c < 2048; c += 256) {
        int row = c >> 4, seg = c & 15;
        float4 v = *reinterpret_cast<float4*>(&stage[row * 68 + seg * 4]);
        *reinterpret_cast<float4*>(outF + ((size_t)b * Lc + l0 + row) * Ec + h * Dc + seg * 4) = v;
    }
}

// ---------------- launch ----------------
extern "C" void kernel_launch(void* const* d_in, const int* in_sizes, int n_in,
                              void* d_out, int out_size) {
    const float* x  = (const float*)d_in[0];
    const float* Wq = (const float*)d_in[1];
    const float* bq = (const float*)d_in[2];
    const float* Wk = (const float*)d_in[3];
    const float* bk = (const float*)d_in[4];
    const float* Wv = (const float*)d_in[5];
    const float* bv = (const float*)d_in[6];
    float* out = (float*)d_out;

    cudaFuncSetAttribute(k_proj_t,   cudaFuncAttributeMaxDynamicSharedMemorySize, 81920);
    cudaFuncSetAttribute(k_scores_p, cudaFuncAttributeMaxDynamicSharedMemorySize, SC_SMEM);
    cudaFuncSetAttribute(k_pv_t,     cudaFuncAttributeMaxDynamicSharedMemorySize, 110592);

    conv_x<<<Mr * Ec / 1024, 256>>>(x);
    conv_w<<<dim3(32, 32, 3), dim3(32, 8)>>>(Wq, Wk, Wv);
    k_proj_t<<<dim3(8, 32, 3), 256, 81920>>>(bq, bk, bv);
    k_scores_p<<<dim3(SC_GRID), 256, SC_SMEM>>>();
    k_vscale<<<dim3(32, 32), 256>>>();
    k_pv_t<<<dim3(16, 32), 256, 110592>>>(out);
}

// round 13
// speedup vs baseline: 1.1689x; 1.0794x over previous
#include <cuda_runtime.h>
#include <cuda_bf16.h>
#include <cstdint>

// ---------------- problem constants ----------------
constexpr int Lc = 2048, Ec = 1024, Hc = 16, Dc = 64, Bc = 2;
constexpr int BHc = Bc * Hc;     // 32
constexpr int Mr  = Bc * Lc;     // 4096
constexpr float LOG2E = 1.4426950408889634f;

// ---------------- device scratch ----------------
__device__ __nv_bfloat16 g_xhi[Mr * Ec],  g_xlo[Mr * Ec];
__device__ __nv_bfloat16 g_wthi[3 * Ec * Ec], g_wtlo[3 * Ec * Ec];
__device__ __nv_bfloat16 g_qhi[BHc * Lc * Dc], g_qlo[BHc * Lc * Dc];   // pre-scaled by log2e
__device__ __nv_bfloat16 g_khi[BHc * Lc * Dc], g_klo[BHc * Lc * Dc];
__device__ float         g_v  [BHc * Lc * Dc];
__device__ __nv_bfloat16 g_vthi[BHc * Dc * Lc], g_vtlo[BHc * Dc * Lc];
__device__ __nv_bfloat16 g_ehi[(size_t)BHc * Lc * Lc];   // 268MB
__device__ __nv_bfloat16 g_elo[(size_t)BHc * Lc * Lc];   // 268MB
__device__ float         g_psum[(size_t)BHc * 16 * Lc];

// ---------------- helpers ----------------
__device__ __forceinline__ uint32_t smem_u32(const void* p) {
    uint32_t a;
    asm("{ .reg .u64 t; cvta.to.shared.u64 t, %1; cvt.u32.u64 %0, t; }" : "=r"(a) : "l"(p));
    return a;
}
__device__ __forceinline__ void split_bf(float f, __nv_bfloat16& h, __nv_bfloat16& l) {
    h = __float2bfloat16(f);
    l = __float2bfloat16(f - __bfloat162float(h));
}
__device__ __forceinline__ void pack_hilo(float f0, float f1, uint32_t& ph, uint32_t& pl) {
    asm("cvt.rn.bf16x2.f32 %0, %1, %2;" : "=r"(ph) : "f"(f1), "f"(f0));
    float h0 = __uint_as_float(ph << 16);
    float h1 = __uint_as_float(ph & 0xFFFF0000u);
    float r0 = f0 - h0, r1 = f1 - h1;
    asm("cvt.rn.bf16x2.f32 %0, %1, %2;" : "=r"(pl) : "f"(r1), "f"(r0));
}
__device__ __forceinline__ void cp16(uint32_t dst, const void* src) {
    asm volatile("cp.async.cg.shared.global [%0], [%1], 16;" :: "r"(dst), "l"(src));
}
__device__ __forceinline__ void cp_commit() { asm volatile("cp.async.commit_group;"); }
template<int N> __device__ __forceinline__ void cp_wait() {
    asm volatile("cp.async.wait_group %0;" :: "n"(N));
}
#define LDSM4(r, addr) \
    asm volatile("ldmatrix.sync.aligned.m8n8.x4.shared.b16 {%0,%1,%2,%3}, [%4];" \
        : "=r"((r)[0]), "=r"((r)[1]), "=r"((r)[2]), "=r"((r)[3]) : "r"(addr))
#define MMA(d, a, b) \
    asm volatile("mma.sync.aligned.m16n8k16.row.col.f32.bf16.bf16.f32 " \
        "{%0,%1,%2,%3}, {%4,%5,%6,%7}, {%8,%9}, {%0,%1,%2,%3};" \
        : "+f"((d)[0]), "+f"((d)[1]), "+f"((d)[2]), "+f"((d)[3]) \
        : "r"((a)[0]), "r"((a)[1]), "r"((a)[2]), "r"((a)[3]), "r"((b)[0]), "r"((b)[1]))

// ---------------- generic 3-term bf16 GEMM core (2-stage) ----------------
template<int BM, int BN, int WGN, int WM, int BKt>
__device__ __forceinline__ void gemm_core(
    const __nv_bfloat16* __restrict__ Ahi, const __nv_bfloat16* __restrict__ Alo, int lda,
    const __nv_bfloat16* __restrict__ Bhi, const __nv_bfloat16* __restrict__ Blo, int ldb,
    int K, uint32_t sb, float* acc)
{
    constexpr int WNB = BN / WGN;
    constexpr int MT  = WM / 16;
    constexpr int NT  = WNB / 8;
    constexpr int PITCH = BKt * 2 + 16;
    constexpr int CPR = BKt / 8;
    constexpr int ABY = BM * PITCH;
    constexpr int BBY = BN * PITCH;
    constexpr int STG = 2 * ABY + 2 * BBY;

    const int tid = threadIdx.x;
    const int wid = tid >> 5, lane = tid & 31;
    const int wm = wid / WGN, wn = wid % WGN;

    auto issue = [&](int it, int buf) {
        const int k0 = it * BKt;
        const uint32_t base = sb + buf * STG;
        #pragma unroll
        for (int c = tid; c < BM * CPR; c += 256) {
            int row = c / CPR, seg = c % CPR;
            uint32_t d = base + row * PITCH + seg * 16;
            cp16(d,       Ahi + (size_t)row * lda + k0 + seg * 8);
            cp16(d + ABY, Alo + (size_t)row * lda + k0 + seg * 8);
        }
        #pragma unroll
        for (int c = tid; c < BN * CPR; c += 256) {
            int row = c / CPR, seg = c % CPR;
            uint32_t d = base + 2 * ABY + row * PITCH + seg * 16;
            cp16(d,       Bhi + (size_t)row * ldb + k0 + seg * 8);
            cp16(d + BBY, Blo + (size_t)row * ldb + k0 + seg * 8);
        }
        cp_commit();
    };

    auto compute = [&](int buf) {
        const uint32_t aB = sb + buf * STG +
            (uint32_t)((wm * WM + (lane & 15)) * PITCH + ((lane >> 4) << 4));
        const uint32_t bB = sb + buf * STG + 2 * ABY +
            (uint32_t)((wn * WNB + (lane & 7) + (((lane >> 4) & 1) << 3)) * PITCH +
                       (((lane >> 3) & 1) << 4));
        #pragma unroll
        for (int ks = 0; ks < BKt / 16; ks++) {
            uint32_t ah[MT][4], al[MT][4];
            #pragma unroll
            for (int mt = 0; mt < MT; mt++) {
                LDSM4(ah[mt], aB + mt * 16 * PITCH + ks * 32);
                LDSM4(al[mt], aB + ABY + mt * 16 * PITCH + ks * 32);
            }
            uint32_t bh[NT][2], bl[NT][2];
            #pragma unroll
            for (int np = 0; np < NT / 2; np++) {
                uint32_t t[4];
                LDSM4(t, bB + np * 16 * PITCH + ks * 32);
                bh[2*np][0] = t[0]; bh[2*np][1] = t[1];
                bh[2*np+1][0] = t[2]; bh[2*np+1][1] = t[3];
                LDSM4(t, bB + BBY + np * 16 * PITCH + ks * 32);
                bl[2*np][0] = t[0]; bl[2*np][1] = t[1];
                bl[2*np+1][0] = t[2]; bl[2*np+1][1] = t[3];
            }
            #pragma unroll
            for (int mt = 0; mt < MT; mt++)
                #pragma unroll
                for (int nt = 0; nt < NT; nt++) {
                    float* d = acc + (mt * NT + nt) * 4;
                    MMA(d, ah[mt], bh[nt]);
                    MMA(d, ah[mt], bl[nt]);
                    MMA(d, al[mt], bh[nt]);
                }
        }
    };

    const int niter = K / BKt;
    issue(0, 0);
    for (int it = 0; it < niter; it++) {
        if (it + 1 < niter) { issue(it + 1, (it + 1) & 1); cp_wait<1>(); }
        else                { cp_wait<0>(); }
        __syncthreads();
        compute(it & 1);
        __syncthreads();
    }
}

// ---------------- conversion kernels ----------------
__global__ void conv_x(const float* __restrict__ x) {
    int i = blockIdx.x * 256 + threadIdx.x;
    float4 v = reinterpret_cast<const float4*>(x)[i];
    uint32_t h01, l01, h23, l23;
    pack_hilo(v.x, v.y, h01, l01);
    pack_hilo(v.z, v.w, h23, l23);
    reinterpret_cast<uint32_t*>(g_xhi)[i * 2]     = h01;
    reinterpret_cast<uint32_t*>(g_xhi)[i * 2 + 1] = h23;
    reinterpret_cast<uint32_t*>(g_xlo)[i * 2]     = l01;
    reinterpret_cast<uint32_t*>(g_xlo)[i * 2 + 1] = l23;
}

__global__ void conv_w(const float* __restrict__ Wq, const float* __restrict__ Wk,
                       const float* __restrict__ Wv) {
    const float* W = (blockIdx.z == 0) ? Wq : (blockIdx.z == 1) ? Wk : Wv;
    __nv_bfloat16* dh = g_wthi + (size_t)blockIdx.z * Ec * Ec;
    __nv_bfloat16* dl = g_wtlo + (size_t)blockIdx.z * Ec * Ec;
    __shared__ float t[32][33];
    int tx = threadIdx.x, ty = threadIdx.y;
    int k0 = blockIdx.x * 32, n0 = blockIdx.y * 32;
    #pragma unroll
    for (int i = 0; i < 4; i++)
        t[ty + i * 8][tx] = W[(size_t)(k0 + ty + i * 8) * Ec + n0 + tx];
    __syncthreads();
    #pragma unroll
    for (int i = 0; i < 4; i++) {
        float v = t[tx][ty + i * 8];
        __nv_bfloat16 h, l; split_bf(v, h, l);
        size_t o = (size_t)(n0 + ty + i * 8) * Ec + k0 + tx;
        dh[o] = h; dl[o] = l;
    }
}

// ---------------- GEMM 1: QKV projection (128x128 tile) ----------------
__global__ void __launch_bounds__(256) k_proj_t(const float* __restrict__ bq,
                                                const float* __restrict__ bk,
                                                const float* __restrict__ bv) {
    extern __shared__ char smem[];
    uint32_t sb = smem_u32(smem);
    const int tid = threadIdx.x;
    const int z = blockIdx.z;
    const int n0 = blockIdx.x * 128, m0 = blockIdx.y * 128;
    const float* bias = (z == 0) ? bq : (z == 1) ? bk : bv;
    const __nv_bfloat16* Whi = g_wthi + (size_t)z * Ec * Ec;
    const __nv_bfloat16* Wlo = g_wtlo + (size_t)z * Ec * Ec;
    const float scl = (z == 0) ? LOG2E : 1.0f;

    float acc[64] = {};
    gemm_core<128, 128, 4, 64, 32>(g_xhi + (size_t)m0 * Ec, g_xlo + (size_t)m0 * Ec, Ec,
                                   Whi + (size_t)n0 * Ec,   Wlo + (size_t)n0 * Ec,   Ec,
                                   Ec, sb, acc);

    float* stage = reinterpret_cast<float*>(smem);   // 128 x pitch130
    const int wid = tid >> 5, lane = tid & 31;
    const int wm = wid >> 2, wn = wid & 3;
    #pragma unroll
    for (int mt = 0; mt < 4; mt++)
        #pragma unroll
        for (int nt = 0; nt < 4; nt++) {
            int r0 = wm * 64 + mt * 16 + (lane >> 2);
            int c0 = wn * 32 + nt * 8 + (lane & 3) * 2;
            float* d = acc + (mt * 4 + nt) * 4;
            stage[r0 * 130 + c0] = d[0]; stage[r0 * 130 + c0 + 1] = d[1];
            stage[(r0 + 8) * 130 + c0] = d[2]; stage[(r0 + 8) * 130 + c0 + 1] = d[3];
        }
    __syncthreads();

    if (z < 2) {
        __nv_bfloat16* dh = (z == 0) ? g_qhi : g_khi;
        __nv_bfloat16* dl = (z == 0) ? g_qlo : g_klo;
        #pragma unroll
        for (int head = 0; head < 2; head++) {
            int h = (n0 >> 6) + head;
            for (int c = tid; c < 1024; c += 256) {
                int row = c >> 3, seg = c & 7;
                int m = m0 + row, b = m >> 11, l = m & 2047;
                uint32_t ph[4], pl[4];
                #pragma unroll
                for (int j = 0; j < 4; j++) {
                    float f0 = (stage[row * 130 + head * 64 + seg * 8 + 2 * j] +
                                bias[n0 + head * 64 + seg * 8 + 2 * j]) * scl;
                    float f1 = (stage[row * 130 + head * 64 + seg * 8 + 2 * j + 1] +
                                bias[n0 + head * 64 + seg * 8 + 2 * j + 1]) * scl;
                    pack_hilo(f0, f1, ph[j], pl[j]);
                }
                size_t o = ((size_t)(b * Hc + h) * Lc + l) * Dc + seg * 8;
                *reinterpret_cast<uint4*>(dh + o) = make_uint4(ph[0], ph[1], ph[2], ph[3]);
                *reinterpret_cast<uint4*>(dl + o) = make_uint4(pl[0], pl[1], pl[2], pl[3]);
            }
        }
    } else {
        for (int c = tid; c < 4096; c += 256) {
            int row = c >> 5, sg = c & 31;
            int head = sg >> 4, seg = sg & 15;
            int m = m0 + row, b = m >> 11, l = m & 2047;
            int h = (n0 >> 6) + head;
            float4 v;
            v.x = stage[row * 130 + head * 64 + seg * 4 + 0] + bias[n0 + head * 64 + seg * 4 + 0];
            v.y = stage[row * 130 + head * 64 + seg * 4 + 1] + bias[n0 + head * 64 + seg * 4 + 1];
            v.z = stage[row * 130 + head * 64 + seg * 4 + 2] + bias[n0 + head * 64 + seg * 4 + 2];
            v.w = stage[row * 130 + head * 64 + seg * 4 + 3] + bias[n0 + head * 64 + seg * 4 + 3];
            *reinterpret_cast<float4*>(g_v + ((size_t)(b * Hc + h) * Lc + l) * Dc + seg * 4) = v;
        }
    }
}

// ---------------- GEMM 2: scores + exp2 + column partial sums (R7 config) ----------------
__global__ void __launch_bounds__(256) k_scores_t() {
    extern __shared__ char smem[];
    uint32_t sb = smem_u32(smem);
    const int tid = threadIdx.x;
    const int bh = blockIdx.z, m0 = blockIdx.x * 128, l0 = blockIdx.y * 128;

    float acc[64] = {};
    gemm_core<128, 128, 4, 64, 32>(g_qhi + ((size_t)bh * Lc + l0) * Dc,
                                   g_qlo + ((size_t)bh * Lc + l0) * Dc, Dc,
                                   g_khi + ((size_t)bh * Lc + m0) * Dc,
                                   g_klo + ((size_t)bh * Lc + m0) * Dc, Dc,
                                   Dc, sb, acc);

    uint32_t* stH = reinterpret_cast<uint32_t*>(smem);            // [128][68]
    uint32_t* stL = stH + 128 * 68;
    float* colp = reinterpret_cast<float*>(stL + 128 * 68);       // [2][128]
    const int wid = tid >> 5, lane = tid & 31;
    const int wm = wid >> 2, wn = wid & 3;

    float cs[4][2] = {};
    #pragma unroll
    for (int mt = 0; mt < 4; mt++)
        #pragma unroll
        for (int nt = 0; nt < 4; nt++) {
            float* d = acc + (mt * 4 + nt) * 4;
            int r0 = wm * 64 + mt * 16 + (lane >> 2);
            int cp = wn * 16 + nt * 4 + (lane & 3);
            float e0 = exp2f(d[0]), e1 = exp2f(d[1]);
            float e2 = exp2f(d[2]), e3 = exp2f(d[3]);
            cs[nt][0] += e0 + e2;
            cs[nt][1] += e1 + e3;
            uint32_t ph, pl;
            pack_hilo(e0, e1, ph, pl);
            stH[r0 * 68 + cp] = ph; stL[r0 * 68 + cp] = pl;
            pack_hilo(e2, e3, ph, pl);
            stH[(r0 + 8) * 68 + cp] = ph; stL[(r0 + 8) * 68 + cp] = pl;
        }

    #pragma unroll
    for (int nt = 0; nt < 4; nt++)
        #pragma unroll
        for (int p = 0; p < 2; p++) {
            float v = cs[nt][p];
            v += __shfl_xor_sync(0xffffffffu, v, 4);
            v += __shfl_xor_sync(0xffffffffu, v, 8);
            v += __shfl_xor_sync(0xffffffffu, v, 16);
            cs[nt][p] = v;
        }
    if (lane < 4) {
        #pragma unroll
        for (int nt = 0; nt < 4; nt++) {
            int cp = wn * 16 + nt * 4 + lane;
            colp[wm * 128 + cp * 2]     = cs[nt][0];
            colp[wm * 128 + cp * 2 + 1] = cs[nt][1];
        }
    }
    __syncthreads();
    if (tid < 128)
        g_psum[((size_t)bh * 16 + blockIdx.y) * Lc + m0 + tid] = colp[tid] + colp[128 + tid];

    for (int c = tid; c < 2048; c += 256) {      // 128 rows x 16 uint4
        int row = c >> 4, seg = c & 15;
        size_t o = ((size_t)bh * Lc + l0 + row) * Lc + m0 + seg * 8;
        *reinterpret_cast<uint4*>(g_ehi + o) =
            *reinterpret_cast<uint4*>(&stH[row * 68 + seg * 4]);
        *reinterpret_cast<uint4*>(g_elo + o) =
            *reinterpret_cast<uint4*>(&stL[row * 68 + seg * 4]);
    }
}

// ---------------- Vs^T = (V * dinv)^T as bf16 hi/lo (dinv fused) ----------------
__global__ void k_vscale() {
    __shared__ float tv[64][65];
    __shared__ float dsm[64];
    int tid = threadIdx.x;
    int bh = blockIdx.y, m0 = blockIdx.x * 64;
    if (tid < 64) {
        float s = 0.0f;
        #pragma unroll
        for (int j = 0; j < 16; j++) s += g_psum[((size_t)bh * 16 + j) * Lc + m0 + tid];
        dsm[tid] = 1.0f / s;
    }
    __syncthreads();
    const float* V = g_v + ((size_t)bh * Lc + m0) * Dc;
    #pragma unroll
    for (int i = 0; i < 16; i++) {
        int e = tid + i * 256;
        int r = e >> 6, d = e & 63;
        tv[r][d] = V[r * Dc + d] * dsm[r];
    }
    __syncthreads();
    #pragma unroll
    for (int i = 0; i < 16; i++) {
        int e = tid + i * 256;
        int d = e >> 6, c = e & 63;
        float v = tv[c][d];
        __nv_bfloat16 h, l; split_bf(v, h, l);
        size_t o = ((size_t)bh * Dc + d) * Lc + m0 + c;
        g_vthi[o] = h; g_vtlo[o] = l;
    }
}

// ---------------- GEMM 3: out = E * Vs^T (128x64, BK=64) ----------------
__global__ void __launch_bounds__(256) k_pv_t(float* __restrict__ outF) {
    extern __shared__ char smem[];
    uint32_t sb = smem_u32(smem);
    const int tid = threadIdx.x;
    const int bh = blockIdx.y, b = bh >> 4, h = bh & 15;
    const int l0 = blockIdx.x * 128;

    float acc[32] = {};
    gemm_core<128, 64, 2, 32, 64>(g_ehi + ((size_t)bh * Lc + l0) * Lc,
                                  g_elo + ((size_t)bh * Lc + l0) * Lc, Lc,
                                  g_vthi + (size_t)bh * Dc * Lc,
                                  g_vtlo + (size_t)bh * Dc * Lc,       Lc,
                                  Lc, sb, acc);

    float* stage = reinterpret_cast<float*>(smem);     // 128 x pitch68
    const int wid = tid >> 5, lane = tid & 31;
    const int wm = wid >> 1, wn = wid & 1;
    #pragma unroll
    for (int mt = 0; mt < 2; mt++)
        #pragma unroll
        for (int nt = 0; nt < 4; nt++) {
            int r0 = wm * 32 + mt * 16 + (lane >> 2);
            int c0 = wn * 32 + nt * 8 + (lane & 3) * 2;
            float* d = acc + (mt * 4 + nt) * 4;
            stage[r0 * 68 + c0] = d[0]; stage[r0 * 68 + c0 + 1] = d[1];
            stage[(r0 + 8) * 68 + c0] = d[2]; stage[(r0 + 8) * 68 + c0 + 1] = d[3];
        }
    __syncthreads();
    for (int c = tid; c < 2048; c += 256) {
        int row = c >> 4, seg = c & 15;
        float4 v = *reinterpret_cast<float4*>(&stage[row * 68 + seg * 4]);
        *reinterpret_cast<float4*>(outF + ((size_t)b * Lc + l0 + row) * Ec + h * Dc + seg * 4) = v;
    }
}

// ---------------- launch ----------------
extern "C" void kernel_launch(void* const* d_in, const int* in_sizes, int n_in,
                              void* d_out, int out_size) {
    const float* x  = (const float*)d_in[0];
    const float* Wq = (const float*)d_in[1];
    const float* bq = (const float*)d_in[2];
    const float* Wk = (const float*)d_in[3];
    const float* bk = (const float*)d_in[4];
    const float* Wv = (const float*)d_in[5];
    const float* bv = (const float*)d_in[6];
    float* out = (float*)d_out;

    cudaFuncSetAttribute(k_proj_t,   cudaFuncAttributeMaxDynamicSharedMemorySize, 81920);
    cudaFuncSetAttribute(k_scores_t, cudaFuncAttributeMaxDynamicSharedMemorySize, 81920);
    cudaFuncSetAttribute(k_pv_t,     cudaFuncAttributeMaxDynamicSharedMemorySize, 110592);

    conv_x<<<Mr * Ec / 1024, 256>>>(x);
    conv_w<<<dim3(32, 32, 3), dim3(32, 8)>>>(Wq, Wk, Wv);
    k_proj_t<<<dim3(8, 32, 3), 256, 81920>>>(bq, bk, bv);
    k_scores_t<<<dim3(16, 16, 32), 256, 81920>>>();
    k_vscale<<<dim3(32, 32), 256>>>();
    k_pv_t<<<dim3(16, 32), 256, 110592>>>(out);
}

// round 14
// speedup vs baseline: 1.2532x; 1.0721x over previous
#include <cuda_runtime.h>
#include <cuda_bf16.h>
#include <cstdint>

// ---------------- problem constants ----------------
constexpr int Lc = 2048, Ec = 1024, Hc = 16, Dc = 64, Bc = 2;
constexpr int BHc = Bc * Hc;     // 32
constexpr int Mr  = Bc * Lc;     // 4096
constexpr float LOG2E = 1.4426950408889634f;

// ---------------- device scratch ----------------
__device__ __nv_bfloat16 g_xhi[Mr * Ec],  g_xlo[Mr * Ec];
__device__ __nv_bfloat16 g_wthi[3 * Ec * Ec], g_wtlo[3 * Ec * Ec];
__device__ __nv_bfloat16 g_qhi[BHc * Lc * Dc], g_qlo[BHc * Lc * Dc];   // pre-scaled by log2e
__device__ __nv_bfloat16 g_khi[BHc * Lc * Dc], g_klo[BHc * Lc * Dc];
__device__ float         g_v  [BHc * Lc * Dc];
__device__ __nv_bfloat16 g_vthi[BHc * Dc * Lc], g_vtlo[BHc * Dc * Lc];
__device__ __nv_bfloat16 g_ehi[(size_t)BHc * Lc * Lc];   // 268MB
__device__ __nv_bfloat16 g_elo[(size_t)BHc * Lc * Lc];   // 268MB
__device__ float         g_psum[(size_t)BHc * 16 * Lc];

// ---------------- helpers ----------------
__device__ __forceinline__ uint32_t smem_u32(const void* p) {
    uint32_t a;
    asm("{ .reg .u64 t; cvta.to.shared.u64 t, %1; cvt.u32.u64 %0, t; }" : "=r"(a) : "l"(p));
    return a;
}
__device__ __forceinline__ void split_bf(float f, __nv_bfloat16& h, __nv_bfloat16& l) {
    h = __float2bfloat16(f);
    l = __float2bfloat16(f - __bfloat162float(h));
}
__device__ __forceinline__ void pack_hilo(float f0, float f1, uint32_t& ph, uint32_t& pl) {
    asm("cvt.rn.bf16x2.f32 %0, %1, %2;" : "=r"(ph) : "f"(f1), "f"(f0));
    float h0 = __uint_as_float(ph << 16);
    float h1 = __uint_as_float(ph & 0xFFFF0000u);
    float r0 = f0 - h0, r1 = f1 - h1;
    asm("cvt.rn.bf16x2.f32 %0, %1, %2;" : "=r"(pl) : "f"(r1), "f"(r0));
}
__device__ __forceinline__ void cp16(uint32_t dst, const void* src) {
    asm volatile("cp.async.cg.shared.global [%0], [%1], 16;" :: "r"(dst), "l"(src));
}
__device__ __forceinline__ void cp_commit() { asm volatile("cp.async.commit_group;"); }
template<int N> __device__ __forceinline__ void cp_wait() {
    asm volatile("cp.async.wait_group %0;" :: "n"(N));
}
#define LDSM4(r, addr) \
    asm volatile("ldmatrix.sync.aligned.m8n8.x4.shared.b16 {%0,%1,%2,%3}, [%4];" \
        : "=r"((r)[0]), "=r"((r)[1]), "=r"((r)[2]), "=r"((r)[3]) : "r"(addr))
#define MMA(d, a, b) \
    asm volatile("mma.sync.aligned.m16n8k16.row.col.f32.bf16.bf16.f32 " \
        "{%0,%1,%2,%3}, {%4,%5,%6,%7}, {%8,%9}, {%0,%1,%2,%3};" \
        : "+f"((d)[0]), "+f"((d)[1]), "+f"((d)[2]), "+f"((d)[3]) \
        : "r"((a)[0]), "r"((a)[1]), "r"((a)[2]), "r"((a)[3]), "r"((b)[0]), "r"((b)[1]))

// ---------------- generic 3-term bf16 GEMM core (2-stage) ----------------
template<int BM, int BN, int WGN, int WM, int BKt>
__device__ __forceinline__ void gemm_core(
    const __nv_bfloat16* __restrict__ Ahi, const __nv_bfloat16* __restrict__ Alo, int lda,
    const __nv_bfloat16* __restrict__ Bhi, const __nv_bfloat16* __restrict__ Blo, int ldb,
    int K, uint32_t sb, float* acc)
{
    constexpr int WNB = BN / WGN;
    constexpr int MT  = WM / 16;
    constexpr int NT  = WNB / 8;
    constexpr int PITCH = BKt * 2 + 16;
    constexpr int CPR = BKt / 8;
    constexpr int ABY = BM * PITCH;
    constexpr int BBY = BN * PITCH;
    constexpr int STG = 2 * ABY + 2 * BBY;

    const int tid = threadIdx.x;
    const int wid = tid >> 5, lane = tid & 31;
    const int wm = wid / WGN, wn = wid % WGN;

    auto issue = [&](int it, int buf) {
        const int k0 = it * BKt;
        const uint32_t base = sb + buf * STG;
        #pragma unroll
        for (int c = tid; c < BM * CPR; c += 256) {
            int row = c / CPR, seg = c % CPR;
            uint32_t d = base + row * PITCH + seg * 16;
            cp16(d,       Ahi + (size_t)row * lda + k0 + seg * 8);
            cp16(d + ABY, Alo + (size_t)row * lda + k0 + seg * 8);
        }
        #pragma unroll
        for (int c = tid; c < BN * CPR; c += 256) {
            int row = c / CPR, seg = c % CPR;
            uint32_t d = base + 2 * ABY + row * PITCH + seg * 16;
            cp16(d,       Bhi + (size_t)row * ldb + k0 + seg * 8);
            cp16(d + BBY, Blo + (size_t)row * ldb + k0 + seg * 8);
        }
        cp_commit();
    };

    auto compute = [&](int buf) {
        const uint32_t aB = sb + buf * STG +
            (uint32_t)((wm * WM + (lane & 15)) * PITCH + ((lane >> 4) << 4));
        const uint32_t bB = sb + buf * STG + 2 * ABY +
            (uint32_t)((wn * WNB + (lane & 7) + (((lane >> 4) & 1) << 3)) * PITCH +
                       (((lane >> 3) & 1) << 4));
        #pragma unroll
        for (int ks = 0; ks < BKt / 16; ks++) {
            uint32_t ah[MT][4], al[MT][4];
            #pragma unroll
            for (int mt = 0; mt < MT; mt++) {
                LDSM4(ah[mt], aB + mt * 16 * PITCH + ks * 32);
                LDSM4(al[mt], aB + ABY + mt * 16 * PITCH + ks * 32);
            }
            uint32_t bh[NT][2], bl[NT][2];
            #pragma unroll
            for (int np = 0; np < NT / 2; np++) {
                uint32_t t[4];
                LDSM4(t, bB + np * 16 * PITCH + ks * 32);
                bh[2*np][0] = t[0]; bh[2*np][1] = t[1];
                bh[2*np+1][0] = t[2]; bh[2*np+1][1] = t[3];
                LDSM4(t, bB + BBY + np * 16 * PITCH + ks * 32);
                bl[2*np][0] = t[0]; bl[2*np][1] = t[1];
                bl[2*np+1][0] = t[2]; bl[2*np+1][1] = t[3];
            }
            #pragma unroll
            for (int mt = 0; mt < MT; mt++)
                #pragma unroll
                for (int nt = 0; nt < NT; nt++) {
                    float* d = acc + (mt * NT + nt) * 4;
                    MMA(d, ah[mt], bh[nt]);
                    MMA(d, ah[mt], bl[nt]);
                    MMA(d, al[mt], bh[nt]);
                }
        }
    };

    const int niter = K / BKt;
    issue(0, 0);
    for (int it = 0; it < niter; it++) {
        if (it + 1 < niter) { issue(it + 1, (it + 1) & 1); cp_wait<1>(); }
        else                { cp_wait<0>(); }
        __syncthreads();
        compute(it & 1);
        __syncthreads();
    }
}

// ---------------- conversion kernels ----------------
__global__ void conv_x(const float* __restrict__ x) {
    int i = blockIdx.x * 256 + threadIdx.x;
    float4 v = reinterpret_cast<const float4*>(x)[i];
    uint32_t h01, l01, h23, l23;
    pack_hilo(v.x, v.y, h01, l01);
    pack_hilo(v.z, v.w, h23, l23);
    reinterpret_cast<uint32_t*>(g_xhi)[i * 2]     = h01;
    reinterpret_cast<uint32_t*>(g_xhi)[i * 2 + 1] = h23;
    reinterpret_cast<uint32_t*>(g_xlo)[i * 2]     = l01;
    reinterpret_cast<uint32_t*>(g_xlo)[i * 2 + 1] = l23;
}

__global__ void conv_w(const float* __restrict__ Wq, const float* __restrict__ Wk,
                       const float* __restrict__ Wv) {
    const float* W = (blockIdx.z == 0) ? Wq : (blockIdx.z == 1) ? Wk : Wv;
    __nv_bfloat16* dh = g_wthi + (size_t)blockIdx.z * Ec * Ec;
    __nv_bfloat16* dl = g_wtlo + (size_t)blockIdx.z * Ec * Ec;
    __shared__ float t[32][33];
    int tx = threadIdx.x, ty = threadIdx.y;
    int k0 = blockIdx.x * 32, n0 = blockIdx.y * 32;
    #pragma unroll
    for (int i = 0; i < 4; i++)
        t[ty + i * 8][tx] = W[(size_t)(k0 + ty + i * 8) * Ec + n0 + tx];
    __syncthreads();
    #pragma unroll
    for (int i = 0; i < 4; i++) {
        float v = t[tx][ty + i * 8];
        __nv_bfloat16 h, l; split_bf(v, h, l);
        size_t o = (size_t)(n0 + ty + i * 8) * Ec + k0 + tx;
        dh[o] = h; dl[o] = l;
    }
}

// ---------------- GEMM 1: QKV projection (128x64 tile, BK=64) ----------------
__global__ void __launch_bounds__(256) k_proj_t(const float* __restrict__ bq,
                                                const float* __restrict__ bk,
                                                const float* __restrict__ bv) {
    extern __shared__ char smem[];
    uint32_t sb = smem_u32(smem);
    const int tid = threadIdx.x;
    const int z = blockIdx.z;
    const int n0 = blockIdx.x * 64, m0 = blockIdx.y * 128;
    const float* bias = (z == 0) ? bq : (z == 1) ? bk : bv;
    const __nv_bfloat16* Whi = g_wthi + (size_t)z * Ec * Ec;
    const __nv_bfloat16* Wlo = g_wtlo + (size_t)z * Ec * Ec;
    const float scl = (z == 0) ? LOG2E : 1.0f;

    float acc[32] = {};
    gemm_core<128, 64, 2, 32, 64>(g_xhi + (size_t)m0 * Ec, g_xlo + (size_t)m0 * Ec, Ec,
                                  Whi + (size_t)n0 * Ec,   Wlo + (size_t)n0 * Ec,   Ec,
                                  Ec, sb, acc);

    float* stage = reinterpret_cast<float*>(smem);   // 128 x pitch68
    const int wid = tid >> 5, lane = tid & 31;
    const int wm = wid >> 1, wn = wid & 1;
    #pragma unroll
    for (int mt = 0; mt < 2; mt++)
        #pragma unroll
        for (int nt = 0; nt < 4; nt++) {
            int r0 = wm * 32 + mt * 16 + (lane >> 2);
            int c0 = wn * 32 + nt * 8 + (lane & 3) * 2;
            float* d = acc + (mt * 4 + nt) * 4;
            stage[r0 * 68 + c0] = d[0]; stage[r0 * 68 + c0 + 1] = d[1];
            stage[(r0 + 8) * 68 + c0] = d[2]; stage[(r0 + 8) * 68 + c0 + 1] = d[3];
        }
    __syncthreads();

    const int h = n0 >> 6;   // single head per block
    if (z < 2) {
        __nv_bfloat16* dh = (z == 0) ? g_qhi : g_khi;
        __nv_bfloat16* dl = (z == 0) ? g_qlo : g_klo;
        for (int c = tid; c < 1024; c += 256) {      // 128 rows x 8 chunks(16B)
            int row = c >> 3, seg = c & 7;
            int m = m0 + row, b = m >> 11, l = m & 2047;
            uint32_t ph[4], pl[4];
            #pragma unroll
            for (int j = 0; j < 4; j++) {
                float f0 = (stage[row * 68 + seg * 8 + 2 * j] +
                            bias[n0 + seg * 8 + 2 * j]) * scl;
                float f1 = (stage[row * 68 + seg * 8 + 2 * j + 1] +
                            bias[n0 + seg * 8 + 2 * j + 1]) * scl;
                pack_hilo(f0, f1, ph[j], pl[j]);
            }
            size_t o = ((size_t)(b * Hc + h) * Lc + l) * Dc + seg * 8;
            *reinterpret_cast<uint4*>(dh + o) = make_uint4(ph[0], ph[1], ph[2], ph[3]);
            *reinterpret_cast<uint4*>(dl + o) = make_uint4(pl[0], pl[1], pl[2], pl[3]);
        }
    } else {
        for (int c = tid; c < 2048; c += 256) {      // 128 rows x 16 float4
            int row = c >> 4, seg = c & 15;
            int m = m0 + row, b = m >> 11, l = m & 2047;
            float4 v;
            v.x = stage[row * 68 + seg * 4 + 0] + bias[n0 + seg * 4 + 0];
            v.y = stage[row * 68 + seg * 4 + 1] + bias[n0 + seg * 4 + 1];
            v.z = stage[row * 68 + seg * 4 + 2] + bias[n0 + seg * 4 + 2];
            v.w = stage[row * 68 + seg * 4 + 3] + bias[n0 + seg * 4 + 3];
            *reinterpret_cast<float4*>(g_v + ((size_t)(b * Hc + h) * Lc + l) * Dc + seg * 4) = v;
        }
    }
}

// ---------------- GEMM 2: scores + exp2 + column partial sums (champion config) ----------------
__global__ void __launch_bounds__(256) k_scores_t() {
    extern __shared__ char smem[];
    uint32_t sb = smem_u32(smem);
    const int tid = threadIdx.x;
    const int bh = blockIdx.z, m0 = blockIdx.x * 128, l0 = blockIdx.y * 128;

    float acc[64] = {};
    gemm_core<128, 128, 4, 64, 32>(g_qhi + ((size_t)bh * Lc + l0) * Dc,
                                   g_qlo + ((size_t)bh * Lc + l0) * Dc, Dc,
                                   g_khi + ((size_t)bh * Lc + m0) * Dc,
                                   g_klo + ((size_t)bh * Lc + m0) * Dc, Dc,
                                   Dc, sb, acc);

    uint32_t* stH = reinterpret_cast<uint32_t*>(smem);            // [128][68]
    uint32_t* stL = stH + 128 * 68;
    float* colp = reinterpret_cast<float*>(stL + 128 * 68);       // [2][128]
    const int wid = tid >> 5, lane = tid & 31;
    const int wm = wid >> 2, wn = wid & 3;

    float cs[4][2] = {};
    #pragma unroll
    for (int mt = 0; mt < 4; mt++)
        #pragma unroll
        for (int nt = 0; nt < 4; nt++) {
            float* d = acc + (mt * 4 + nt) * 4;
            int r0 = wm * 64 + mt * 16 + (lane >> 2);
            int cp = wn * 16 + nt * 4 + (lane & 3);
            float e0 = exp2f(d[0]), e1 = exp2f(d[1]);
            float e2 = exp2f(d[2]), e3 = exp2f(d[3]);
            cs[nt][0] += e0 + e2;
            cs[nt][1] += e1 + e3;
            uint32_t ph, pl;
            pack_hilo(e0, e1, ph, pl);
            stH[r0 * 68 + cp] = ph; stL[r0 * 68 + cp] = pl;
            pack_hilo(e2, e3, ph, pl);
            stH[(r0 + 8) * 68 + cp] = ph; stL[(r0 + 8) * 68 + cp] = pl;
        }

    #pragma unroll
    for (int nt = 0; nt < 4; nt++)
        #pragma unroll
        for (int p = 0; p < 2; p++) {
            float v = cs[nt][p];
            v += __shfl_xor_sync(0xffffffffu, v, 4);
            v += __shfl_xor_sync(0xffffffffu, v, 8);
            v += __shfl_xor_sync(0xffffffffu, v, 16);
            cs[nt][p] = v;
        }
    if (lane < 4) {
        #pragma unroll
        for (int nt = 0; nt < 4; nt++) {
            int cp = wn * 16 + nt * 4 + lane;
            colp[wm * 128 + cp * 2]     = cs[nt][0];
            colp[wm * 128 + cp * 2 + 1] = cs[nt][1];
        }
    }
    __syncthreads();
    if (tid < 128)
        g_psum[((size_t)bh * 16 + blockIdx.y) * Lc + m0 + tid] = colp[tid] + colp[128 + tid];

    for (int c = tid; c < 2048; c += 256) {      // 128 rows x 16 uint4
        int row = c >> 4, seg = c & 15;
        size_t o = ((size_t)bh * Lc + l0 + row) * Lc + m0 + seg * 8;
        *reinterpret_cast<uint4*>(g_ehi + o) =
            *reinterpret_cast<uint4*>(&stH[row * 68 + seg * 4]);
        *reinterpret_cast<uint4*>(g_elo + o) =
            *reinterpret_cast<uint4*>(&stL[row * 68 + seg * 4]);
    }
}

// ---------------- Vs^T = (V * dinv)^T as bf16 hi/lo (dinv fused) ----------------
__global__ void k_vscale() {
    __shared__ float tv[64][65];
    __shared__ float dsm[64];
    int tid = threadIdx.x;
    int bh = blockIdx.y, m0 = blockIdx.x * 64;
    if (tid < 64) {
        float s = 0.0f;
        #pragma unroll
        for (int j = 0; j < 16; j++) s += g_psum[((size_t)bh * 16 + j) * Lc + m0 + tid];
        dsm[tid] = 1.0f / s;
    }
    __syncthreads();
    const float* V = g_v + ((size_t)bh * Lc + m0) * Dc;
    #pragma unroll
    for (int i = 0; i < 16; i++) {
        int e = tid + i * 256;
        int r = e >> 6, d = e & 63;
        tv[r][d] = V[r * Dc + d] * dsm[r];
    }
    __syncthreads();
    #pragma unroll
    for (int i = 0; i < 16; i++) {
        int e = tid + i * 256;
        int d = e >> 6, c = e & 63;
        float v = tv[c][d];
        __nv_bfloat16 h, l; split_bf(v, h, l);
        size_t o = ((size_t)bh * Dc + d) * Lc + m0 + c;
        g_vthi[o] = h; g_vtlo[o] = l;
    }
}

// ---------------- GEMM 3: out = E * Vs^T (128x64, BK=64) ----------------
__global__ void __launch_bounds__(256) k_pv_t(float* __restrict__ outF) {
    extern __shared__ char smem[];
    uint32_t sb = smem_u32(smem);
    const int tid = threadIdx.x;
    const int bh = blockIdx.y, b = bh >> 4, h = bh & 15;
    const int l0 = blockIdx.x * 128;

    float acc[32] = {};
    gemm_core<128, 64, 2, 32, 64>(g_ehi + ((size_t)bh * Lc + l0) * Lc,
                                  g_elo + ((size_t)bh * Lc + l0) * Lc, Lc,
                                  g_vthi + (size_t)bh * Dc * Lc,
                                  g_vtlo + (size_t)bh * Dc * Lc,       Lc,
                                  Lc, sb, acc);

    float* stage = reinterpret_cast<float*>(smem);     // 128 x pitch68
    const int wid = tid >> 5, lane = tid & 31;
    const int wm = wid >> 1, wn = wid & 1;
    #pragma unroll
    for (int mt = 0; mt < 2; mt++)
        #pragma unroll
        for (int nt = 0; nt < 4; nt++) {
            int r0 = wm * 32 + mt * 16 + (lane >> 2);
            int c0 = wn * 32 + nt * 8 + (lane & 3) * 2;
            float* d = acc + (mt * 4 + nt) * 4;
            stage[r0 * 68 + c0] = d[0]; stage[r0 * 68 + c0 + 1] = d[1];
            stage[(r0 + 8) * 68 + c0] = d[2]; stage[(r0 + 8) * 68 + c0 + 1] = d[3];
        }
    __syncthreads();
    for (int c = tid; c < 2048; c += 256) {
        int row = c >> 4, seg = c & 15;
        float4 v = *reinterpret_cast<float4*>(&stage[row * 68 + seg * 4]);
        *reinterpret_cast<float4*>(outF + ((size_t)b * Lc + l0 + row) * Ec + h * Dc + seg * 4) = v;
    }
}

// ---------------- launch ----------------
extern "C" void kernel_launch(void* const* d_in, const int* in_sizes, int n_in,
                              void* d_out, int out_size) {
    const float* x  = (const float*)d_in[0];
    const float* Wq = (const float*)d_in[1];
    const float* bq = (const float*)d_in[2];
    const float* Wk = (const float*)d_in[3];
    const float* bk = (const float*)d_in[4];
    const float* Wv = (const float*)d_in[5];
    const float* bv = (const float*)d_in[6];
    float* out = (float*)d_out;

    cudaFuncSetAttribute(k_proj_t,   cudaFuncAttributeMaxDynamicSharedMemorySize, 110592);
    cudaFuncSetAttribute(k_scores_t, cudaFuncAttributeMaxDynamicSharedMemorySize, 81920);
    cudaFuncSetAttribute(k_pv_t,     cudaFuncAttributeMaxDynamicSharedMemorySize, 110592);

    conv_x<<<Mr * Ec / 1024, 256>>>(x);
    conv_w<<<dim3(32, 32, 3), dim3(32, 8)>>>(Wq, Wk, Wv);
    k_proj_t<<<dim3(16, 32, 3), 256, 110592>>>(bq, bk, bv);
    k_scores_t<<<dim3(16, 16, 32), 256, 81920>>>();
    k_vscale<<<dim3(32, 32), 256>>>();
    k_pv_t<<<dim3(16, 32), 256, 110592>>>(out);
}

// round 15
// speedup vs baseline: 1.2537x; 1.0004x over previous
#include <cuda_runtime.h>
#include <cuda_bf16.h>
#include <cstdint>

// ---------------- problem constants ----------------
constexpr int Lc = 2048, Ec = 1024, Hc = 16, Dc = 64, Bc = 2;
constexpr int BHc = Bc * Hc;     // 32
constexpr int Mr  = Bc * Lc;     // 4096
constexpr float LOG2E = 1.4426950408889634f;

// ---------------- device scratch ----------------
__device__ __nv_bfloat16 g_xhi[Mr * Ec],  g_xlo[Mr * Ec];
__device__ __nv_bfloat16 g_wthi[3 * Ec * Ec], g_wtlo[3 * Ec * Ec];
__device__ __nv_bfloat16 g_qhi[BHc * Lc * Dc], g_qlo[BHc * Lc * Dc];   // pre-scaled by log2e
__device__ __nv_bfloat16 g_khi[BHc * Lc * Dc], g_klo[BHc * Lc * Dc];
__device__ float         g_v  [BHc * Lc * Dc];
__device__ __nv_bfloat16 g_vthi[BHc * Dc * Lc], g_vtlo[BHc * Dc * Lc];
__device__ __nv_bfloat16 g_ehi[(size_t)BHc * Lc * Lc];   // 268MB
__device__ __nv_bfloat16 g_elo[(size_t)BHc * Lc * Lc];   // 268MB
__device__ float         g_psum[(size_t)BHc * 16 * Lc];

// ---------------- helpers ----------------
__device__ __forceinline__ uint32_t smem_u32(const void* p) {
    uint32_t a;
    asm("{ .reg .u64 t; cvta.to.shared.u64 t, %1; cvt.u32.u64 %0, t; }" : "=r"(a) : "l"(p));
    return a;
}
__device__ __forceinline__ void split_bf(float f, __nv_bfloat16& h, __nv_bfloat16& l) {
    h = __float2bfloat16(f);
    l = __float2bfloat16(f - __bfloat162float(h));
}
__device__ __forceinline__ void pack_hilo(float f0, float f1, uint32_t& ph, uint32_t& pl) {
    asm("cvt.rn.bf16x2.f32 %0, %1, %2;" : "=r"(ph) : "f"(f1), "f"(f0));
    float h0 = __uint_as_float(ph << 16);
    float h1 = __uint_as_float(ph & 0xFFFF0000u);
    float r0 = f0 - h0, r1 = f1 - h1;
    asm("cvt.rn.bf16x2.f32 %0, %1, %2;" : "=r"(pl) : "f"(r1), "f"(r0));
}
__device__ __forceinline__ void cp16(uint32_t dst, const void* src) {
    asm volatile("cp.async.cg.shared.global [%0], [%1], 16;" :: "r"(dst), "l"(src));
}
__device__ __forceinline__ void cp_commit() { asm volatile("cp.async.commit_group;"); }
template<int N> __device__ __forceinline__ void cp_wait() {
    asm volatile("cp.async.wait_group %0;" :: "n"(N));
}
#define LDSM4(r, addr) \
    asm volatile("ldmatrix.sync.aligned.m8n8.x4.shared.b16 {%0,%1,%2,%3}, [%4];" \
        : "=r"((r)[0]), "=r"((r)[1]), "=r"((r)[2]), "=r"((r)[3]) : "r"(addr))
#define MMA(d, a, b) \
    asm volatile("mma.sync.aligned.m16n8k16.row.col.f32.bf16.bf16.f32 " \
        "{%0,%1,%2,%3}, {%4,%5,%6,%7}, {%8,%9}, {%0,%1,%2,%3};" \
        : "+f"((d)[0]), "+f"((d)[1]), "+f"((d)[2]), "+f"((d)[3]) \
        : "r"((a)[0]), "r"((a)[1]), "r"((a)[2]), "r"((a)[3]), "r"((b)[0]), "r"((b)[1]))

// ---------------- generic 3-term bf16 GEMM core (2-stage) ----------------
template<int BM, int BN, int WGN, int WM, int BKt>
__device__ __forceinline__ void gemm_core(
    const __nv_bfloat16* __restrict__ Ahi, const __nv_bfloat16* __restrict__ Alo, int lda,
    const __nv_bfloat16* __restrict__ Bhi, const __nv_bfloat16* __restrict__ Blo, int ldb,
    int K, uint32_t sb, float* acc)
{
    constexpr int WNB = BN / WGN;
    constexpr int MT  = WM / 16;
    constexpr int NT  = WNB / 8;
    constexpr int PITCH = BKt * 2 + 16;
    constexpr int CPR = BKt / 8;
    constexpr int ABY = BM * PITCH;
    constexpr int BBY = BN * PITCH;
    constexpr int STG = 2 * ABY + 2 * BBY;

    const int tid = threadIdx.x;
    const int wid = tid >> 5, lane = tid & 31;
    const int wm = wid / WGN, wn = wid % WGN;

    auto issue = [&](int it, int buf) {
        const int k0 = it * BKt;
        const uint32_t base = sb + buf * STG;
        #pragma unroll
        for (int c = tid; c < BM * CPR; c += 256) {
            int row = c / CPR, seg = c % CPR;
            uint32_t d = base + row * PITCH + seg * 16;
            cp16(d,       Ahi + (size_t)row * lda + k0 + seg * 8);
            cp16(d + ABY, Alo + (size_t)row * lda + k0 + seg * 8);
        }
        #pragma unroll
        for (int c = tid; c < BN * CPR; c += 256) {
            int row = c / CPR, seg = c % CPR;
            uint32_t d = base + 2 * ABY + row * PITCH + seg * 16;
            cp16(d,       Bhi + (size_t)row * ldb + k0 + seg * 8);
            cp16(d + BBY, Blo + (size_t)row * ldb + k0 + seg * 8);
        }
        cp_commit();
    };

    auto compute = [&](int buf) {
        const uint32_t aB = sb + buf * STG +
            (uint32_t)((wm * WM + (lane & 15)) * PITCH + ((lane >> 4) << 4));
        const uint32_t bB = sb + buf * STG + 2 * ABY +
            (uint32_t)((wn * WNB + (lane & 7) + (((lane >> 4) & 1) << 3)) * PITCH +
                       (((lane >> 3) & 1) << 4));
        #pragma unroll
        for (int ks = 0; ks < BKt / 16; ks++) {
            uint32_t ah[MT][4], al[MT][4];
            #pragma unroll
            for (int mt = 0; mt < MT; mt++) {
                LDSM4(ah[mt], aB + mt * 16 * PITCH + ks * 32);
                LDSM4(al[mt], aB + ABY + mt * 16 * PITCH + ks * 32);
            }
            uint32_t bh[NT][2], bl[NT][2];
            #pragma unroll
            for (int np = 0; np < NT / 2; np++) {
                uint32_t t[4];
                LDSM4(t, bB + np * 16 * PITCH + ks * 32);
                bh[2*np][0] = t[0]; bh[2*np][1] = t[1];
                bh[2*np+1][0] = t[2]; bh[2*np+1][1] = t[3];
                LDSM4(t, bB + BBY + np * 16 * PITCH + ks * 32);
                bl[2*np][0] = t[0]; bl[2*np][1] = t[1];
                bl[2*np+1][0] = t[2]; bl[2*np+1][1] = t[3];
            }
            #pragma unroll
            for (int mt = 0; mt < MT; mt++)
                #pragma unroll
                for (int nt = 0; nt < NT; nt++) {
                    float* d = acc + (mt * NT + nt) * 4;
                    MMA(d, ah[mt], bh[nt]);
                    MMA(d, ah[mt], bl[nt]);
                    MMA(d, al[mt], bh[nt]);
                }
        }
    };

    const int niter = K / BKt;
    issue(0, 0);
    for (int it = 0; it < niter; it++) {
        if (it + 1 < niter) { issue(it + 1, (it + 1) & 1); cp_wait<1>(); }
        else                { cp_wait<0>(); }
        __syncthreads();
        compute(it & 1);
        __syncthreads();
    }
}

// ---------------- conversion kernels ----------------
__global__ void conv_x(const float* __restrict__ x) {
    int i = blockIdx.x * 256 + threadIdx.x;
    float4 v = reinterpret_cast<const float4*>(x)[i];
    uint32_t h01, l01, h23, l23;
    pack_hilo(v.x, v.y, h01, l01);
    pack_hilo(v.z, v.w, h23, l23);
    reinterpret_cast<uint32_t*>(g_xhi)[i * 2]     = h01;
    reinterpret_cast<uint32_t*>(g_xhi)[i * 2 + 1] = h23;
    reinterpret_cast<uint32_t*>(g_xlo)[i * 2]     = l01;
    reinterpret_cast<uint32_t*>(g_xlo)[i * 2 + 1] = l23;
}

__global__ void conv_w(const float* __restrict__ Wq, const float* __restrict__ Wk,
                       const float* __restrict__ Wv) {
    const float* W = (blockIdx.z == 0) ? Wq : (blockIdx.z == 1) ? Wk : Wv;
    __nv_bfloat16* dh = g_wthi + (size_t)blockIdx.z * Ec * Ec;
    __nv_bfloat16* dl = g_wtlo + (size_t)blockIdx.z * Ec * Ec;
    __shared__ float t[32][33];
    int tx = threadIdx.x, ty = threadIdx.y;
    int k0 = blockIdx.x * 32, n0 = blockIdx.y * 32;
    #pragma unroll
    for (int i = 0; i < 4; i++)
        t[ty + i * 8][tx] = W[(size_t)(k0 + ty + i * 8) * Ec + n0 + tx];
    __syncthreads();
    #pragma unroll
    for (int i = 0; i < 4; i++) {
        float v = t[tx][ty + i * 8];
        __nv_bfloat16 h, l; split_bf(v, h, l);
        size_t o = (size_t)(n0 + ty + i * 8) * Ec + k0 + tx;
        dh[o] = h; dl[o] = l;
    }
}

// ---------------- GEMM 1: QKV projection (128x64 tile, BK=64) ----------------
__global__ void __launch_bounds__(256) k_proj_t(const float* __restrict__ bq,
                                                const float* __restrict__ bk,
                                                const float* __restrict__ bv,
                                                int zbase) {
    extern __shared__ char smem[];
    uint32_t sb = smem_u32(smem);
    const int tid = threadIdx.x;
    const int z = blockIdx.z + zbase;
    const int n0 = blockIdx.x * 64, m0 = blockIdx.y * 128;
    const float* bias = (z == 0) ? bq : (z == 1) ? bk : bv;
    const __nv_bfloat16* Whi = g_wthi + (size_t)z * Ec * Ec;
    const __nv_bfloat16* Wlo = g_wtlo + (size_t)z * Ec * Ec;
    const float scl = (z == 0) ? LOG2E : 1.0f;

    float acc[32] = {};
    gemm_core<128, 64, 2, 32, 64>(g_xhi + (size_t)m0 * Ec, g_xlo + (size_t)m0 * Ec, Ec,
                                  Whi + (size_t)n0 * Ec,   Wlo + (size_t)n0 * Ec,   Ec,
                                  Ec, sb, acc);

    float* stage = reinterpret_cast<float*>(smem);   // 128 x pitch68
    const int wid = tid >> 5, lane = tid & 31;
    const int wm = wid >> 1, wn = wid & 1;
    #pragma unroll
    for (int mt = 0; mt < 2; mt++)
        #pragma unroll
        for (int nt = 0; nt < 4; nt++) {
            int r0 = wm * 32 + mt * 16 + (lane >> 2);
            int c0 = wn * 32 + nt * 8 + (lane & 3) * 2;
            float* d = acc + (mt * 4 + nt) * 4;
            stage[r0 * 68 + c0] = d[0]; stage[r0 * 68 + c0 + 1] = d[1];
            stage[(r0 + 8) * 68 + c0] = d[2]; stage[(r0 + 8) * 68 + c0 + 1] = d[3];
        }
    __syncthreads();

    const int h = n0 >> 6;   // single head per block
    if (z < 2) {
        __nv_bfloat16* dh = (z == 0) ? g_qhi : g_khi;
        __nv_bfloat16* dl = (z == 0) ? g_qlo : g_klo;
        for (int c = tid; c < 1024; c += 256) {      // 128 rows x 8 chunks(16B)
            int row = c >> 3, seg = c & 7;
            int m = m0 + row, b = m >> 11, l = m & 2047;
            uint32_t ph[4], pl[4];
            #pragma unroll
            for (int j = 0; j < 4; j++) {
                float f0 = (stage[row * 68 + seg * 8 + 2 * j] +
                            bias[n0 + seg * 8 + 2 * j]) * scl;
                float f1 = (stage[row * 68 + seg * 8 + 2 * j + 1] +
                            bias[n0 + seg * 8 + 2 * j + 1]) * scl;
                pack_hilo(f0, f1, ph[j], pl[j]);
            }
            size_t o = ((size_t)(b * Hc + h) * Lc + l) * Dc + seg * 8;
            *reinterpret_cast<uint4*>(dh + o) = make_uint4(ph[0], ph[1], ph[2], ph[3]);
            *reinterpret_cast<uint4*>(dl + o) = make_uint4(pl[0], pl[1], pl[2], pl[3]);
        }
    } else {
        for (int c = tid; c < 2048; c += 256) {      // 128 rows x 16 float4
            int row = c >> 4, seg = c & 15;
            int m = m0 + row, b = m >> 11, l = m & 2047;
            float4 v;
            v.x = stage[row * 68 + seg * 4 + 0] + bias[n0 + seg * 4 + 0];
            v.y = stage[row * 68 + seg * 4 + 1] + bias[n0 + seg * 4 + 1];
            v.z = stage[row * 68 + seg * 4 + 2] + bias[n0 + seg * 4 + 2];
            v.w = stage[row * 68 + seg * 4 + 3] + bias[n0 + seg * 4 + 3];
            *reinterpret_cast<float4*>(g_v + ((size_t)(b * Hc + h) * Lc + l) * Dc + seg * 4) = v;
        }
    }
}

// ---------------- GEMM 2: scores + exp2 + column partial sums ----------------
__global__ void __launch_bounds__(256) k_scores_t() {
    extern __shared__ char smem[];
    uint32_t sb = smem_u32(smem);
    const int tid = threadIdx.x;
    const int bh = blockIdx.z, m0 = blockIdx.x * 128, l0 = blockIdx.y * 128;

    float acc[64] = {};
    gemm_core<128, 128, 4, 64, 32>(g_qhi + ((size_t)bh * Lc + l0) * Dc,
                                   g_qlo + ((size_t)bh * Lc + l0) * Dc, Dc,
                                   g_khi + ((size_t)bh * Lc + m0) * Dc,
                                   g_klo + ((size_t)bh * Lc + m0) * Dc, Dc,
                                   Dc, sb, acc);

    uint32_t* stH = reinterpret_cast<uint32_t*>(smem);            // [128][68]
    uint32_t* stL = stH + 128 * 68;
    float* colp = reinterpret_cast<float*>(stL + 128 * 68);       // [2][128]
    const int wid = tid >> 5, lane = tid & 31;
    const int wm = wid >> 2, wn = wid & 3;

    float cs[4][2] = {};
    #pragma unroll
    for (int mt = 0; mt < 4; mt++)
        #pragma unroll
        for (int nt = 0; nt < 4; nt++) {
            float* d = acc + (mt * 4 + nt) * 4;
            int r0 = wm * 64 + mt * 16 + (lane >> 2);
            int cp = wn * 16 + nt * 4 + (lane & 3);
            float e0 = exp2f(d[0]), e1 = exp2f(d[1]);
            float e2 = exp2f(d[2]), e3 = exp2f(d[3]);
            cs[nt][0] += e0 + e2;
            cs[nt][1] += e1 + e3;
            uint32_t ph, pl;
            pack_hilo(e0, e1, ph, pl);
            stH[r0 * 68 + cp] = ph; stL[r0 * 68 + cp] = pl;
            pack_hilo(e2, e3, ph, pl);
            stH[(r0 + 8) * 68 + cp] = ph; stL[(r0 + 8) * 68 + cp] = pl;
        }

    #pragma unroll
    for (int nt = 0; nt < 4; nt++)
        #pragma unroll
        for (int p = 0; p < 2; p++) {
            float v = cs[nt][p];
            v += __shfl_xor_sync(0xffffffffu, v, 4);
            v += __shfl_xor_sync(0xffffffffu, v, 8);
            v += __shfl_xor_sync(0xffffffffu, v, 16);
            cs[nt][p] = v;
        }
    if (lane < 4) {
        #pragma unroll
        for (int nt = 0; nt < 4; nt++) {
            int cp = wn * 16 + nt * 4 + lane;
            colp[wm * 128 + cp * 2]     = cs[nt][0];
            colp[wm * 128 + cp * 2 + 1] = cs[nt][1];
        }
    }
    __syncthreads();
    if (tid < 128)
        g_psum[((size_t)bh * 16 + blockIdx.y) * Lc + m0 + tid] = colp[tid] + colp[128 + tid];

    for (int c = tid; c < 2048; c += 256) {      // 128 rows x 16 uint4
        int row = c >> 4, seg = c & 15;
        size_t o = ((size_t)bh * Lc + l0 + row) * Lc + m0 + seg * 8;
        *reinterpret_cast<uint4*>(g_ehi + o) =
            *reinterpret_cast<uint4*>(&stH[row * 68 + seg * 4]);
        *reinterpret_cast<uint4*>(g_elo + o) =
            *reinterpret_cast<uint4*>(&stL[row * 68 + seg * 4]);
    }
}

// ---------------- Vs^T = (V * dinv)^T as bf16 hi/lo (dinv fused) ----------------
__global__ void k_vscale() {
    __shared__ float tv[64][65];
    __shared__ float dsm[64];
    int tid = threadIdx.x;
    int bh = blockIdx.y, m0 = blockIdx.x * 64;
    if (tid < 64) {
        float s = 0.0f;
        #pragma unroll
        for (int j = 0; j < 16; j++) s += g_psum[((size_t)bh * 16 + j) * Lc + m0 + tid];
        dsm[tid] = 1.0f / s;
    }
    __syncthreads();
    const float* V = g_v + ((size_t)bh * Lc + m0) * Dc;
    #pragma unroll
    for (int i = 0; i < 16; i++) {
        int e = tid + i * 256;
        int r = e >> 6, d = e & 63;
        tv[r][d] = V[r * Dc + d] * dsm[r];
    }
    __syncthreads();
    #pragma unroll
    for (int i = 0; i < 16; i++) {
        int e = tid + i * 256;
        int d = e >> 6, c = e & 63;
        float v = tv[c][d];
        __nv_bfloat16 h, l; split_bf(v, h, l);
        size_t o = ((size_t)bh * Dc + d) * Lc + m0 + c;
        g_vthi[o] = h; g_vtlo[o] = l;
    }
}

// ---------------- GEMM 3: out = E * Vs^T (128x64, BK=64) ----------------
__global__ void __launch_bounds__(256) k_pv_t(float* __restrict__ outF) {
    extern __shared__ char smem[];
    uint32_t sb = smem_u32(smem);
    const int tid = threadIdx.x;
    const int bh = blockIdx.y, b = bh >> 4, h = bh & 15;
    const int l0 = blockIdx.x * 128;

    float acc[32] = {};
    gemm_core<128, 64, 2, 32, 64>(g_ehi + ((size_t)bh * Lc + l0) * Lc,
                                  g_elo + ((size_t)bh * Lc + l0) * Lc, Lc,
                                  g_vthi + (size_t)bh * Dc * Lc,
                                  g_vtlo + (size_t)bh * Dc * Lc,       Lc,
                                  Lc, sb, acc);

    float* stage = reinterpret_cast<float*>(smem);     // 128 x pitch68
    const int wid = tid >> 5, lane = tid & 31;
    const int wm = wid >> 1, wn = wid & 1;
    #pragma unroll
    for (int mt = 0; mt < 2; mt++)
        #pragma unroll
        for (int nt = 0; nt < 4; nt++) {
            int r0 = wm * 32 + mt * 16 + (lane >> 2);
            int c0 = wn * 32 + nt * 8 + (lane & 3) * 2;
            float* d = acc + (mt * 4 + nt) * 4;
            stage[r0 * 68 + c0] = d[0]; stage[r0 * 68 + c0 + 1] = d[1];
            stage[(r0 + 8) * 68 + c0] = d[2]; stage[(r0 + 8) * 68 + c0 + 1] = d[3];
        }
    __syncthreads();
    for (int c = tid; c < 2048; c += 256) {
        int row = c >> 4, seg = c & 15;
        float4 v = *reinterpret_cast<float4*>(&stage[row * 68 + seg * 4]);
        *reinterpret_cast<float4*>(outF + ((size_t)b * Lc + l0 + row) * Ec + h * Dc + seg * 4) = v;
    }
}

// ---------------- launch (fork-join overlap: projV || scores) ----------------
extern "C" void kernel_launch(void* const* d_in, const int* in_sizes, int n_in,
                              void* d_out, int out_size) {
    const float* x  = (const float*)d_in[0];
    const float* Wq = (const float*)d_in[1];
    const float* bq = (const float*)d_in[2];
    const float* Wk = (const float*)d_in[3];
    const float* bk = (const float*)d_in[4];
    const float* Wv = (const float*)d_in[5];
    const float* bv = (const float*)d_in[6];
    float* out = (float*)d_out;

    static bool init_done = false;
    static cudaStream_t s1;
    static cudaEvent_t ev0, evX, evW, evV;
    if (!init_done) {
        cudaStreamCreateWithFlags(&s1, cudaStreamNonBlocking);
        cudaEventCreateWithFlags(&ev0, cudaEventDisableTiming);
        cudaEventCreateWithFlags(&evX, cudaEventDisableTiming);
        cudaEventCreateWithFlags(&evW, cudaEventDisableTiming);
        cudaEventCreateWithFlags(&evV, cudaEventDisableTiming);
        cudaFuncSetAttribute(k_proj_t,   cudaFuncAttributeMaxDynamicSharedMemorySize, 110592);
        cudaFuncSetAttribute(k_scores_t, cudaFuncAttributeMaxDynamicSharedMemorySize, 81920);
        cudaFuncSetAttribute(k_pv_t,     cudaFuncAttributeMaxDynamicSharedMemorySize, 110592);
        init_done = true;
    }

    // fork: conv_x on s1, conv_w on default
    cudaEventRecord(ev0, 0);
    cudaStreamWaitEvent(s1, ev0, 0);
    conv_x<<<Mr * Ec / 1024, 256, 0, s1>>>(x);
    cudaEventRecord(evX, s1);

    conv_w<<<dim3(32, 32, 3), dim3(32, 8)>>>(Wq, Wk, Wv);
    cudaEventRecord(evW, 0);

    // default: wait for conv_x, then projQK -> scores
    cudaStreamWaitEvent(0, evX, 0);
    k_proj_t<<<dim3(16, 32, 2), 256, 110592>>>(bq, bk, bv, 0);

    // s1: wait for conv_w, run projV concurrently with projQK/scores
    cudaStreamWaitEvent(s1, evW, 0);
    k_proj_t<<<dim3(16, 32, 1), 256, 110592, s1>>>(bq, bk, bv, 2);
    cudaEventRecord(evV, s1);

    k_scores_t<<<dim3(16, 16, 32), 256, 81920>>>();

    // join: vscale needs psum (scores, default) + g_v (projV, s1)
    cudaStreamWaitEvent(0, evV, 0);
    k_vscale<<<dim3(32, 32), 256>>>();
    k_pv_t<<<dim3(16, 32), 256, 110592>>>(out);
}